// round 1
// baseline (speedup 1.0000x reference)
#include <cuda_runtime.h>
#include <math.h>

#define NN   20000
#define NE   320000
#define NG   64
#define DIN  1280
#define DH   512
#define DFC  1024
#define DOUT 5000

// ---------------- scratch (static device memory; no allocs) ----------------
__device__ float g_h   [NN * DH];   // GEMM output (pre-aggregation features)
__device__ float g_agg [NN * DH];   // aggregation accumulator
__device__ float g_h2  [NN * DH];   // layer-2 GEMM output
__device__ float g_dinv[NN];        // deg^{-1/2} (also used as deg accumulator)
__device__ float g_pool[NG * DH];   // pooled graph features
__device__ float g_fc1 [NG * DFC];  // fc1 activations
__device__ int   g_is64;            // edge_index/batch dtype flag

// ---------------- dtype detection (int64 vs int32 indices) ----------------
__global__ void k_detect(const void* ei) {
    const long long* p = (const long long*)ei;
    int ok = 1;
#pragma unroll
    for (int i = 0; i < 8; i++) {
        long long v = p[i];
        if (v < 0 || v >= NN) ok = 0;
    }
    g_is64 = ok;
}

__device__ __forceinline__ int idx_at(const void* p, long long i) {
    return g_is64 ? (int)((const long long*)p)[i] : ((const int*)p)[i];
}

// ---------------- degree / dinv ----------------
__global__ void k_init_deg() {
    int i = blockIdx.x * blockDim.x + threadIdx.x;
    if (i < NN) g_dinv[i] = 1.0f;  // self-loop
}

__global__ void k_deg(const void* __restrict__ ei) {
    int e = blockIdx.x * blockDim.x + threadIdx.x;
    if (e < NE) {
        int dst = idx_at(ei, (long long)NE + e);
        atomicAdd(&g_dinv[dst], 1.0f);
    }
}

__global__ void k_rsqrt() {
    int i = blockIdx.x * blockDim.x + threadIdx.x;
    if (i < NN) g_dinv[i] = rsqrtf(g_dinv[i]);
}

// ---------------- main SGEMM: C = A @ B ; AGG = C * dinv[row]^2 ----------------
// BM=128, BN=128, BK=8, 256 threads, 8x8 per thread.
__global__ void __launch_bounds__(256) k_gemm(
    const float* __restrict__ A, const float* __restrict__ B,
    float* __restrict__ C, float* __restrict__ AGG,
    int M, int N, int K)
{
    __shared__ float As[8][128];
    __shared__ float Bs[8][128];

    const int tid = threadIdx.x;
    const int rowBase = blockIdx.x * 128;
    const int colBase = blockIdx.y * 128;

    // A loader: 128 rows x 8 k, float4 along K
    const int aRow = tid >> 1;
    const int aCol = (tid & 1) * 4;
    // B loader: 8 k rows x 128 cols, float4 along N
    const int bRow = tid >> 5;
    const int bCol = (tid & 31) * 4;

    const int tx = tid & 15;
    const int ty = tid >> 4;

    float acc[8][8];
#pragma unroll
    for (int i = 0; i < 8; i++)
#pragma unroll
        for (int j = 0; j < 8; j++) acc[i][j] = 0.0f;

    const bool aValid = (rowBase + aRow) < M;
    const float* Aptr = A + (size_t)(rowBase + aRow) * K + aCol;
    const float* Bptr = B + (size_t)bRow * N + colBase + bCol;

    for (int k0 = 0; k0 < K; k0 += 8) {
        float4 a = aValid ? *(const float4*)Aptr : make_float4(0.f, 0.f, 0.f, 0.f);
        float4 b = *(const float4*)Bptr;

        __syncthreads();
        As[aCol + 0][aRow] = a.x;
        As[aCol + 1][aRow] = a.y;
        As[aCol + 2][aRow] = a.z;
        As[aCol + 3][aRow] = a.w;
        *(float4*)&Bs[bRow][bCol] = b;
        __syncthreads();

#pragma unroll
        for (int k = 0; k < 8; k++) {
            float4 a0 = *(const float4*)&As[k][ty * 8];
            float4 a1 = *(const float4*)&As[k][ty * 8 + 4];
            float4 b0 = *(const float4*)&Bs[k][tx * 8];
            float4 b1 = *(const float4*)&Bs[k][tx * 8 + 4];
            float ra[8] = {a0.x, a0.y, a0.z, a0.w, a1.x, a1.y, a1.z, a1.w};
            float rb[8] = {b0.x, b0.y, b0.z, b0.w, b1.x, b1.y, b1.z, b1.w};
#pragma unroll
            for (int i = 0; i < 8; i++)
#pragma unroll
                for (int j = 0; j < 8; j++)
                    acc[i][j] = fmaf(ra[i], rb[j], acc[i][j]);
        }

        Aptr += 8;
        Bptr += (size_t)8 * N;
    }

    const int row0 = rowBase + ty * 8;
    const int col0 = colBase + tx * 8;
#pragma unroll
    for (int i = 0; i < 8; i++) {
        int row = row0 + i;
        if (row < M) {
            float d = g_dinv[row];
            float d2 = d * d;
            float4 c0 = make_float4(acc[i][0], acc[i][1], acc[i][2], acc[i][3]);
            float4 c1 = make_float4(acc[i][4], acc[i][5], acc[i][6], acc[i][7]);
            *(float4*)(C + (size_t)row * N + col0)     = c0;
            *(float4*)(C + (size_t)row * N + col0 + 4) = c1;
            float4 g0 = make_float4(c0.x * d2, c0.y * d2, c0.z * d2, c0.w * d2);
            float4 g1 = make_float4(c1.x * d2, c1.y * d2, c1.z * d2, c1.w * d2);
            *(float4*)(AGG + (size_t)row * N + col0)     = g0;
            *(float4*)(AGG + (size_t)row * N + col0 + 4) = g1;
        }
    }
}

// ---------------- edge scatter: agg[dst] += h[src] * dinv[src]*dinv[dst] ----------------
// blockDim = (128, 2): 128 threads cover 512 cols via float4; 2 edges per block.
__global__ void __launch_bounds__(256) k_scatter(const float* __restrict__ h,
                                                 const void* __restrict__ ei)
{
    int e = blockIdx.x * 2 + threadIdx.y;
    if (e >= NE) return;
    int src, dst;
    if (g_is64) {
        const long long* p = (const long long*)ei;
        src = (int)p[e];
        dst = (int)p[NE + e];
    } else {
        const int* p = (const int*)ei;
        src = p[e];
        dst = p[NE + e];
    }
    float coef = g_dinv[src] * g_dinv[dst];
    int c = threadIdx.x * 4;
    float4 v = *(const float4*)(h + (size_t)src * DH + c);
    float* d = g_agg + (size_t)dst * DH + c;
    atomicAdd(d + 0, v.x * coef);
    atomicAdd(d + 1, v.y * coef);
    atomicAdd(d + 2, v.z * coef);
    atomicAdd(d + 3, v.w * coef);
}

// ---------------- bias + relu: out = relu(agg + b) ----------------
__global__ void k_bias_relu(const float* __restrict__ bias, float* __restrict__ out) {
    int t = blockIdx.x * blockDim.x + threadIdx.x;
    int row = t >> 7;
    int c = (t & 127) * 4;
    if (row < NN) {
        float4 v = *(const float4*)(g_agg + (size_t)row * DH + c);
        float4 b = *(const float4*)(bias + c);
        v.x = fmaxf(v.x + b.x, 0.f);
        v.y = fmaxf(v.y + b.y, 0.f);
        v.z = fmaxf(v.z + b.z, 0.f);
        v.w = fmaxf(v.w + b.w, 0.f);
        *(float4*)(out + (size_t)row * DH + c) = v;
    }
}

// ---------------- fused bias+relu+segment_max over sorted batch ----------------
__device__ __forceinline__ int lower_bound_batch(const void* batch, int val) {
    int lo = 0, hi = NN;
    while (lo < hi) {
        int mid = (lo + hi) >> 1;
        if (idx_at(batch, mid) < val) lo = mid + 1; else hi = mid;
    }
    return lo;
}

__global__ void k_segmax(const void* __restrict__ batch, const float* __restrict__ bias) {
    int g = blockIdx.x;
    int c = threadIdx.x;  // 512
    int s = lower_bound_batch(batch, g);
    int e = lower_bound_batch(batch, g + 1);
    float b = bias[c];
    float m = 0.0f;  // relu output >= 0, non-empty segments guaranteed
    for (int n = s; n < e; n++) {
        float v = g_agg[(size_t)n * DH + c] + b;
        m = fmaxf(m, v);
    }
    g_pool[g * DH + c] = fmaxf(m, 0.0f);
}

// ---------------- FC head GEMM (M=64), mode 0: relu, mode 1: bn+sigmoid ----------------
__global__ void __launch_bounds__(256) k_head(
    const float* __restrict__ A, const float* __restrict__ B,
    const float* __restrict__ bias, float* __restrict__ C,
    int N, int K, int mode,
    const float* __restrict__ gamma, const float* __restrict__ beta)
{
    const int BK = 32, BN = 32;
    __shared__ float As[BK][64];
    __shared__ float Bs[BK][BN];

    int tid = threadIdx.x;
    int colBase = blockIdx.x * BN;
    int ty = tid >> 4, tx = tid & 15;

    float acc[4][2] = {{0.f, 0.f}, {0.f, 0.f}, {0.f, 0.f}, {0.f, 0.f}};

    for (int k0 = 0; k0 < K; k0 += BK) {
        __syncthreads();
#pragma unroll
        for (int l = 0; l < 8; l++) {
            int idx = tid * 8 + l;       // 0..2047
            int m = idx >> 5, k = idx & 31;
            As[k][m] = A[(size_t)m * K + k0 + k];
        }
#pragma unroll
        for (int l = 0; l < 4; l++) {
            int idx = tid * 4 + l;       // 0..1023
            int k = idx >> 5, n = idx & 31;
            int col = colBase + n;
            Bs[k][n] = (col < N) ? B[(size_t)(k0 + k) * N + col] : 0.f;
        }
        __syncthreads();
#pragma unroll
        for (int k = 0; k < BK; k++) {
            float ra[4], rb[2];
#pragma unroll
            for (int i = 0; i < 4; i++) ra[i] = As[k][ty * 4 + i];
#pragma unroll
            for (int j = 0; j < 2; j++) rb[j] = Bs[k][tx * 2 + j];
#pragma unroll
            for (int i = 0; i < 4; i++)
#pragma unroll
                for (int j = 0; j < 2; j++)
                    acc[i][j] = fmaf(ra[i], rb[j], acc[i][j]);
        }
    }

    const float bninv = rsqrtf(1.0f + 1e-5f);
#pragma unroll
    for (int i = 0; i < 4; i++) {
#pragma unroll
        for (int j = 0; j < 2; j++) {
            int row = ty * 4 + i;
            int col = colBase + tx * 2 + j;
            if (col < N) {
                float z = acc[i][j] + bias[col];
                if (mode == 0) {
                    z = fmaxf(z, 0.f);
                } else {
                    z = z * gamma[col] * bninv + beta[col];
                    z = 1.0f / (1.0f + expf(-z));
                }
                C[(size_t)row * N + col] = z;
            }
        }
    }
}

// ---------------- host ----------------
extern "C" void kernel_launch(void* const* d_in, const int* in_sizes, int n_in,
                              void* d_out, int out_size)
{
    const float* x     = (const float*)d_in[0];
    const void*  ei    = d_in[1];
    const void*  batch = d_in[2];
    const float* Wg1   = (const float*)d_in[3];
    const float* bg1   = (const float*)d_in[4];
    const float* Wg2   = (const float*)d_in[5];
    const float* bg2   = (const float*)d_in[6];
    const float* W1    = (const float*)d_in[7];
    const float* b1    = (const float*)d_in[8];
    const float* W2    = (const float*)d_in[9];
    const float* b2    = (const float*)d_in[10];
    const float* gamma = (const float*)d_in[11];
    const float* beta  = (const float*)d_in[12];
    float* out = (float*)d_out;

    float *p_h, *p_h2, *p_pool, *p_fc1;
    cudaGetSymbolAddress((void**)&p_h,    g_h);
    cudaGetSymbolAddress((void**)&p_h2,   g_h2);
    cudaGetSymbolAddress((void**)&p_pool, g_pool);
    cudaGetSymbolAddress((void**)&p_fc1,  g_fc1);
    float* p_agg;
    cudaGetSymbolAddress((void**)&p_agg, g_agg);

    // 0. index dtype detection
    k_detect<<<1, 1>>>(ei);

    // 1. degrees -> dinv
    k_init_deg<<<(NN + 255) / 256, 256>>>();
    k_deg<<<(NE + 255) / 256, 256>>>(ei);
    k_rsqrt<<<(NN + 255) / 256, 256>>>();

    // 2. layer 1: h = x @ Wg1 ; agg = h * dinv^2 (self loop)
    dim3 g1((NN + 127) / 128, DH / 128);
    k_gemm<<<g1, 256>>>(x, Wg1, p_h, p_agg, NN, DH, DIN);
    k_scatter<<<NE / 2, dim3(128, 2)>>>(p_h, ei);
    k_bias_relu<<<(NN * (DH / 4) + 255) / 256, 256>>>(bg1, p_h);

    // 3. layer 2
    k_gemm<<<g1, 256>>>(p_h, Wg2, p_h2, p_agg, NN, DH, DH);
    k_scatter<<<NE / 2, dim3(128, 2)>>>(p_h2, ei);

    // 4. pooled relu-max (bias bg2 fused)
    k_segmax<<<NG, DH>>>(batch, bg2);

    // 5. FC head
    k_head<<<(DFC + 31) / 32, 256>>>(p_pool, W1, b1, p_fc1, DFC, DH, 0, nullptr, nullptr);
    k_head<<<(DOUT + 31) / 32, 256>>>(p_fc1, W2, b2, out, DOUT, DFC, 1, gamma, beta);
}

// round 2
// speedup vs baseline: 1.4647x; 1.4647x over previous
#include <cuda_runtime.h>
#include <math.h>

#define NN   20000
#define NE   320000
#define NG   64
#define DIN  1280
#define DH   512
#define DFC  1024
#define DOUT 5000

// ---------------- scratch (static device memory; no allocs) ----------------
__device__ float g_h   [NN * DH];   // layer-1 GEMM output
__device__ float g_agg [NN * DH];   // aggregation output (both layers)
__device__ float g_h2  [NN * DH];   // layer-2 GEMM output
__device__ float g_dinv[NN];        // deg^{-1/2}
__device__ int   g_cnt [NN];        // in-degree counts
__device__ int   g_rowptr[NN + 1];  // CSR row pointers (by dst)
__device__ int   g_cursor[NN];      // fill cursors
__device__ int   g_csrsrc[NE];      // CSR: src node per incoming edge
__device__ float g_pool[NG * DH];   // pooled graph features
__device__ float g_fc1 [NG * DFC];  // fc1 activations
__device__ int   g_is64;            // edge_index/batch dtype flag

// ---------------- dtype detection (int64 vs int32 indices) ----------------
__global__ void k_detect(const void* ei) {
    const long long* p = (const long long*)ei;
    int ok = 1;
#pragma unroll
    for (int i = 0; i < 8; i++) {
        long long v = p[i];
        if (v < 0 || v >= NN) ok = 0;
    }
    g_is64 = ok;
}

__device__ __forceinline__ int idx_at(const void* p, long long i) {
    return g_is64 ? (int)((const long long*)p)[i] : ((const int*)p)[i];
}

// ---------------- degree count ----------------
__global__ void k_zero_cnt() {
    int i = blockIdx.x * blockDim.x + threadIdx.x;
    if (i < NN) g_cnt[i] = 0;
}

__global__ void k_deg(const void* __restrict__ ei) {
    int e = blockIdx.x * blockDim.x + threadIdx.x;
    if (e < NE) {
        int dst = idx_at(ei, (long long)NE + e);
        atomicAdd(&g_cnt[dst], 1);
    }
}

__global__ void k_rsqrt() {
    int i = blockIdx.x * blockDim.x + threadIdx.x;
    if (i < NN) g_dinv[i] = rsqrtf((float)g_cnt[i] + 1.0f);
}

// ---------------- single-block exclusive scan of g_cnt -> rowptr/cursor ----------------
#define SCAN_T   1024
#define SCAN_CH  20           // 1024*20 = 20480 >= NN
__global__ void __launch_bounds__(SCAN_T) k_scan() {
    __shared__ int s[SCAN_T];
    int tid = threadIdx.x;
    int base = tid * SCAN_CH;
    int local[SCAN_CH];
    int sum = 0;
#pragma unroll
    for (int i = 0; i < SCAN_CH; i++) {
        int idx = base + i;
        int v = (idx < NN) ? g_cnt[idx] : 0;
        local[i] = sum;
        sum += v;
    }
    s[tid] = sum;
    __syncthreads();
    for (int off = 1; off < SCAN_T; off <<= 1) {
        int v = (tid >= off) ? s[tid - off] : 0;
        __syncthreads();
        if (tid >= off) s[tid] += v;
        __syncthreads();
    }
    int pre = (tid > 0) ? s[tid - 1] : 0;
#pragma unroll
    for (int i = 0; i < SCAN_CH; i++) {
        int idx = base + i;
        if (idx < NN) {
            int v = pre + local[i];
            g_rowptr[idx] = v;
            g_cursor[idx] = v;
        }
    }
    if (tid == SCAN_T - 1) g_rowptr[NN] = NE;
}

// ---------------- CSR fill ----------------
__global__ void k_fill(const void* __restrict__ ei) {
    int e = blockIdx.x * blockDim.x + threadIdx.x;
    if (e < NE) {
        int src, dst;
        if (g_is64) {
            const long long* p = (const long long*)ei;
            src = (int)p[e];
            dst = (int)p[NE + e];
        } else {
            const int* p = (const int*)ei;
            src = p[e];
            dst = p[NE + e];
        }
        int pos = atomicAdd(&g_cursor[dst], 1);
        g_csrsrc[pos] = src;
    }
}

// ---------------- main SGEMM: C = A @ B (128x128x8, 256 thr, 8x8/thr) ----------------
__global__ void __launch_bounds__(256) k_gemm(
    const float* __restrict__ A, const float* __restrict__ B,
    float* __restrict__ C, int M, int N, int K)
{
    __shared__ float As[8][128];
    __shared__ float Bs[8][128];

    const int tid = threadIdx.x;
    const int rowBase = blockIdx.x * 128;
    const int colBase = blockIdx.y * 128;

    const int aRow = tid >> 1;
    const int aCol = (tid & 1) * 4;
    const int bRow = tid >> 5;
    const int bCol = (tid & 31) * 4;

    const int tx = tid & 15;
    const int ty = tid >> 4;

    float acc[8][8];
#pragma unroll
    for (int i = 0; i < 8; i++)
#pragma unroll
        for (int j = 0; j < 8; j++) acc[i][j] = 0.0f;

    const bool aValid = (rowBase + aRow) < M;
    const float* Aptr = A + (size_t)(rowBase + aRow) * K + aCol;
    const float* Bptr = B + (size_t)bRow * N + colBase + bCol;

    for (int k0 = 0; k0 < K; k0 += 8) {
        float4 a = aValid ? *(const float4*)Aptr : make_float4(0.f, 0.f, 0.f, 0.f);
        float4 b = *(const float4*)Bptr;

        __syncthreads();
        As[aCol + 0][aRow] = a.x;
        As[aCol + 1][aRow] = a.y;
        As[aCol + 2][aRow] = a.z;
        As[aCol + 3][aRow] = a.w;
        *(float4*)&Bs[bRow][bCol] = b;
        __syncthreads();

#pragma unroll
        for (int k = 0; k < 8; k++) {
            float4 a0 = *(const float4*)&As[k][ty * 8];
            float4 a1 = *(const float4*)&As[k][ty * 8 + 4];
            float4 b0 = *(const float4*)&Bs[k][tx * 8];
            float4 b1 = *(const float4*)&Bs[k][tx * 8 + 4];
            float ra[8] = {a0.x, a0.y, a0.z, a0.w, a1.x, a1.y, a1.z, a1.w};
            float rb[8] = {b0.x, b0.y, b0.z, b0.w, b1.x, b1.y, b1.z, b1.w};
#pragma unroll
            for (int i = 0; i < 8; i++)
#pragma unroll
                for (int j = 0; j < 8; j++)
                    acc[i][j] = fmaf(ra[i], rb[j], acc[i][j]);
        }

        Aptr += 8;
        Bptr += (size_t)8 * N;
    }

    const int row0 = rowBase + ty * 8;
    const int col0 = colBase + tx * 8;
#pragma unroll
    for (int i = 0; i < 8; i++) {
        int row = row0 + i;
        if (row < M) {
            *(float4*)(C + (size_t)row * N + col0) =
                make_float4(acc[i][0], acc[i][1], acc[i][2], acc[i][3]);
            *(float4*)(C + (size_t)row * N + col0 + 4) =
                make_float4(acc[i][4], acc[i][5], acc[i][6], acc[i][7]);
        }
    }
}

// ---------------- CSR gather aggregation ----------------
// out[n] = (relu?) ( sum_{src in N(n)} h[src]*dinv[src]*dinv[n] + h[n]*dinv[n]^2 + bias )
// blockDim (128, 2): 128 threads x float4 = 512 cols; 2 nodes per block.
__global__ void __launch_bounds__(256) k_gather(
    const float* __restrict__ h, const float* __restrict__ bias,
    float* __restrict__ out, int doRelu)
{
    int n = blockIdx.x * 2 + threadIdx.y;
    if (n >= NN) return;
    int s = g_rowptr[n];
    int e = g_rowptr[n + 1];
    float dn = g_dinv[n];
    int c = threadIdx.x * 4;

    // self-loop
    float4 v = *(const float4*)(h + (size_t)n * DH + c);
    float d2 = dn * dn;
    float4 acc = make_float4(v.x * d2, v.y * d2, v.z * d2, v.w * d2);

    int j = s;
    for (; j + 1 < e; j += 2) {
        int s0 = g_csrsrc[j];
        int s1 = g_csrsrc[j + 1];
        float c0 = g_dinv[s0] * dn;
        float c1 = g_dinv[s1] * dn;
        float4 v0 = *(const float4*)(h + (size_t)s0 * DH + c);
        float4 v1 = *(const float4*)(h + (size_t)s1 * DH + c);
        acc.x = fmaf(v0.x, c0, acc.x); acc.y = fmaf(v0.y, c0, acc.y);
        acc.z = fmaf(v0.z, c0, acc.z); acc.w = fmaf(v0.w, c0, acc.w);
        acc.x = fmaf(v1.x, c1, acc.x); acc.y = fmaf(v1.y, c1, acc.y);
        acc.z = fmaf(v1.z, c1, acc.z); acc.w = fmaf(v1.w, c1, acc.w);
    }
    if (j < e) {
        int s0 = g_csrsrc[j];
        float c0 = g_dinv[s0] * dn;
        float4 v0 = *(const float4*)(h + (size_t)s0 * DH + c);
        acc.x = fmaf(v0.x, c0, acc.x); acc.y = fmaf(v0.y, c0, acc.y);
        acc.z = fmaf(v0.z, c0, acc.z); acc.w = fmaf(v0.w, c0, acc.w);
    }

    float4 b = *(const float4*)(bias + c);
    acc.x += b.x; acc.y += b.y; acc.z += b.z; acc.w += b.w;
    if (doRelu) {
        acc.x = fmaxf(acc.x, 0.f); acc.y = fmaxf(acc.y, 0.f);
        acc.z = fmaxf(acc.z, 0.f); acc.w = fmaxf(acc.w, 0.f);
    }
    *(float4*)(out + (size_t)n * DH + c) = acc;
}

// ---------------- segment max over sorted batch (+ final relu) ----------------
__device__ __forceinline__ int lower_bound_batch(const void* batch, int val) {
    int lo = 0, hi = NN;
    while (lo < hi) {
        int mid = (lo + hi) >> 1;
        if (idx_at(batch, mid) < val) lo = mid + 1; else hi = mid;
    }
    return lo;
}

__global__ void k_segmax(const void* __restrict__ batch) {
    int g = blockIdx.x;
    int c = threadIdx.x;  // 512
    int s = lower_bound_batch(batch, g);
    int e = lower_bound_batch(batch, g + 1);
    float m = 0.0f;  // relu(gcn2) >= 0
    for (int n = s; n < e; n++)
        m = fmaxf(m, g_agg[(size_t)n * DH + c]);
    g_pool[g * DH + c] = m;
}

// ---------------- FC head GEMM (M=64), mode 0: relu, mode 1: bn+sigmoid ----------------
__global__ void __launch_bounds__(256) k_head(
    const float* __restrict__ A, const float* __restrict__ B,
    const float* __restrict__ bias, float* __restrict__ C,
    int N, int K, int mode,
    const float* __restrict__ gamma, const float* __restrict__ beta)
{
    const int BK = 32, BN = 32;
    __shared__ float As[BK][64];
    __shared__ float Bs[BK][BN];

    int tid = threadIdx.x;
    int colBase = blockIdx.x * BN;
    int ty = tid >> 4, tx = tid & 15;

    float acc[4][2] = {{0.f, 0.f}, {0.f, 0.f}, {0.f, 0.f}, {0.f, 0.f}};

    for (int k0 = 0; k0 < K; k0 += BK) {
        __syncthreads();
#pragma unroll
        for (int l = 0; l < 8; l++) {
            int idx = tid * 8 + l;
            int m = idx >> 5, k = idx & 31;
            As[k][m] = A[(size_t)m * K + k0 + k];
        }
#pragma unroll
        for (int l = 0; l < 4; l++) {
            int idx = tid * 4 + l;
            int k = idx >> 5, n = idx & 31;
            int col = colBase + n;
            Bs[k][n] = (col < N) ? B[(size_t)(k0 + k) * N + col] : 0.f;
        }
        __syncthreads();
#pragma unroll
        for (int k = 0; k < BK; k++) {
            float ra[4], rb[2];
#pragma unroll
            for (int i = 0; i < 4; i++) ra[i] = As[k][ty * 4 + i];
#pragma unroll
            for (int j = 0; j < 2; j++) rb[j] = Bs[k][tx * 2 + j];
#pragma unroll
            for (int i = 0; i < 4; i++)
#pragma unroll
                for (int j = 0; j < 2; j++)
                    acc[i][j] = fmaf(ra[i], rb[j], acc[i][j]);
        }
    }

    const float bninv = rsqrtf(1.0f + 1e-5f);
#pragma unroll
    for (int i = 0; i < 4; i++) {
#pragma unroll
        for (int j = 0; j < 2; j++) {
            int row = ty * 4 + i;
            int col = colBase + tx * 2 + j;
            if (col < N) {
                float z = acc[i][j] + bias[col];
                if (mode == 0) {
                    z = fmaxf(z, 0.f);
                } else {
                    z = z * gamma[col] * bninv + beta[col];
                    z = 1.0f / (1.0f + expf(-z));
                }
                C[(size_t)row * N + col] = z;
            }
        }
    }
}

// ---------------- host ----------------
extern "C" void kernel_launch(void* const* d_in, const int* in_sizes, int n_in,
                              void* d_out, int out_size)
{
    const float* x     = (const float*)d_in[0];
    const void*  ei    = d_in[1];
    const void*  batch = d_in[2];
    const float* Wg1   = (const float*)d_in[3];
    const float* bg1   = (const float*)d_in[4];
    const float* Wg2   = (const float*)d_in[5];
    const float* bg2   = (const float*)d_in[6];
    const float* W1    = (const float*)d_in[7];
    const float* b1    = (const float*)d_in[8];
    const float* W2    = (const float*)d_in[9];
    const float* b2    = (const float*)d_in[10];
    const float* gamma = (const float*)d_in[11];
    const float* beta  = (const float*)d_in[12];
    float* out = (float*)d_out;

    float *p_h, *p_h2, *p_agg, *p_pool, *p_fc1;
    cudaGetSymbolAddress((void**)&p_h,    g_h);
    cudaGetSymbolAddress((void**)&p_h2,   g_h2);
    cudaGetSymbolAddress((void**)&p_agg,  g_agg);
    cudaGetSymbolAddress((void**)&p_pool, g_pool);
    cudaGetSymbolAddress((void**)&p_fc1,  g_fc1);

    // 0. index dtype detection
    k_detect<<<1, 1>>>(ei);

    // 1. degree -> dinv, CSR build
    k_zero_cnt<<<(NN + 255) / 256, 256>>>();
    k_deg<<<(NE + 255) / 256, 256>>>(ei);
    k_rsqrt<<<(NN + 255) / 256, 256>>>();
    k_scan<<<1, SCAN_T>>>();
    k_fill<<<(NE + 255) / 256, 256>>>(ei);

    // 2. layer 1: h = x @ Wg1 ; agg = relu(gather(h) + bg1) -> g_agg
    dim3 g1((NN + 127) / 128, DH / 128);
    k_gemm<<<g1, 256>>>(x, Wg1, p_h, NN, DH, DIN);
    k_gather<<<(NN + 1) / 2, dim3(128, 2)>>>(p_h, bg1, p_agg, 1);

    // 3. layer 2: h2 = agg @ Wg2 ; agg = gather(h2) + bg2 (relu folded into segmax)
    k_gemm<<<g1, 256>>>(p_agg, Wg2, p_h2, NN, DH, DH);
    k_gather<<<(NN + 1) / 2, dim3(128, 2)>>>(p_h2, bg2, p_agg, 0);

    // 4. pooled max (+relu)
    k_segmax<<<NG, DH>>>(batch);

    // 5. FC head
    k_head<<<(DFC + 31) / 32, 256>>>(p_pool, W1, b1, p_fc1, DFC, DH, 0, nullptr, nullptr);
    k_head<<<(DOUT + 31) / 32, 256>>>(p_fc1, W2, b2, out, DOUT, DFC, 1, gamma, beta);
}

// round 4
// speedup vs baseline: 2.7484x; 1.8764x over previous
#include <cuda_runtime.h>
#include <math.h>
#include <stdint.h>

#define NN   20000
#define NE   320000
#define NG   64
#define DIN  1280
#define DH   512
#define DFC  1024
#define DOUT 5000

// ---------------- scratch ----------------
__device__ float g_h   [NN * DH];
__device__ float g_agg [NN * DH];
__device__ float g_h2  [NN * DH];
__device__ float g_dinv[NN];
__device__ int   g_cnt [NN];
__device__ int   g_rowptr[NN + 1];
__device__ int   g_cursor[NN];
__device__ int   g_csrsrc[NE];
__device__ float g_pool[NG * DH];
__device__ float g_fc1 [NG * DFC];
__device__ int   g_is64;

// ---------------- dtype detection ----------------
__global__ void k_detect(const void* ei) {
    const long long* p = (const long long*)ei;
    int ok = 1;
#pragma unroll
    for (int i = 0; i < 8; i++) {
        long long v = p[i];
        if (v < 0 || v >= NN) ok = 0;
    }
    g_is64 = ok;
}
__device__ __forceinline__ int idx_at(const void* p, long long i) {
    return g_is64 ? (int)((const long long*)p)[i] : ((const int*)p)[i];
}

// ---------------- degree / CSR ----------------
__global__ void k_zero_cnt() {
    int i = blockIdx.x * blockDim.x + threadIdx.x;
    if (i < NN) g_cnt[i] = 0;
}
__global__ void k_deg(const void* __restrict__ ei) {
    int e = blockIdx.x * blockDim.x + threadIdx.x;
    if (e < NE) atomicAdd(&g_cnt[idx_at(ei, (long long)NE + e)], 1);
}
__global__ void k_rsqrt() {
    int i = blockIdx.x * blockDim.x + threadIdx.x;
    if (i < NN) g_dinv[i] = rsqrtf((float)g_cnt[i] + 1.0f);
}

#define SCAN_T   1024
#define SCAN_CH  20
__global__ void __launch_bounds__(SCAN_T) k_scan() {
    __shared__ int s[SCAN_T];
    int tid = threadIdx.x;
    int base = tid * SCAN_CH;
    int local[SCAN_CH];
    int sum = 0;
#pragma unroll
    for (int i = 0; i < SCAN_CH; i++) {
        int idx = base + i;
        int v = (idx < NN) ? g_cnt[idx] : 0;
        local[i] = sum;
        sum += v;
    }
    s[tid] = sum;
    __syncthreads();
    for (int off = 1; off < SCAN_T; off <<= 1) {
        int v = (tid >= off) ? s[tid - off] : 0;
        __syncthreads();
        if (tid >= off) s[tid] += v;
        __syncthreads();
    }
    int pre = (tid > 0) ? s[tid - 1] : 0;
#pragma unroll
    for (int i = 0; i < SCAN_CH; i++) {
        int idx = base + i;
        if (idx < NN) {
            int v = pre + local[i];
            g_rowptr[idx] = v;
            g_cursor[idx] = v;
        }
    }
    if (tid == SCAN_T - 1) g_rowptr[NN] = NE;
}
__global__ void k_fill(const void* __restrict__ ei) {
    int e = blockIdx.x * blockDim.x + threadIdx.x;
    if (e < NE) {
        int src, dst;
        if (g_is64) {
            const long long* p = (const long long*)ei;
            src = (int)p[e]; dst = (int)p[NE + e];
        } else {
            const int* p = (const int*)ei;
            src = p[e]; dst = p[NE + e];
        }
        g_csrsrc[atomicAdd(&g_cursor[dst], 1)] = src;
    }
}

// ---------------- tf32 mma.sync GEMM: C[M,512] = A[M,K] @ B[K,512] ----------------
// BM=128, BN=128, BK=16. 256 threads = 8 warps (2x4). Warp tile 64x32.
// mma.m16n8k8: 4x4 mma tiles per warp per k8-step.
#define SPAD 136   // smem row stride in words (pad 8 -> conflict-free frag loads)

__device__ __forceinline__ uint32_t f2tf(float x) {
    uint32_t r;
    asm("cvt.rna.tf32.f32 %0, %1;" : "=r"(r) : "f"(x));
    return r;
}

__global__ void __launch_bounds__(256, 2) k_gemm_mma(
    const float* __restrict__ A, const float* __restrict__ B,
    float* __restrict__ C, int M, int K)
{
    __shared__ uint32_t As[16][SPAD];  // [k][m]
    __shared__ uint32_t Bs[16][SPAD];  // [k][n]

    const int tid  = threadIdx.x;
    const int wid  = tid >> 5;
    const int lane = tid & 31;
    const int wm   = wid >> 2;       // 0..1
    const int wn   = wid & 3;        // 0..3
    const int m0   = blockIdx.x * 128;
    const int n0   = blockIdx.y * 128;

    // loader mapping
    const int lm    = tid & 127;       // A row within tile
    const int lhalf = tid >> 7;        // 0/1 -> k offset 0/8
    const bool aval = (m0 + lm) < M;
    const float* Ap = A + (size_t)(m0 + lm) * K + lhalf * 8;
    const int bn = (tid & 31) * 4;     // B col within tile
    const int bk = tid >> 5;           // 0..7
    const float* Bp = B + (size_t)bk * DH + n0 + bn;

    float acc[4][4][4];
#pragma unroll
    for (int mi = 0; mi < 4; mi++)
#pragma unroll
        for (int ni = 0; ni < 4; ni++)
#pragma unroll
            for (int q = 0; q < 4; q++) acc[mi][ni][q] = 0.0f;

    float4 ra0, ra1, rb0, rb1;
    // prefetch tile 0
    if (aval) {
        ra0 = *(const float4*)(Ap);
        ra1 = *(const float4*)(Ap + 4);
    } else {
        ra0 = make_float4(0.f, 0.f, 0.f, 0.f);
        ra1 = ra0;
    }
    rb0 = *(const float4*)(Bp);
    rb1 = *(const float4*)(Bp + (size_t)8 * DH);

    const int r = lane >> 2;   // 0..7
    const int c = lane & 3;    // 0..3

    for (int k0 = 0; k0 < K; k0 += 16) {
        __syncthreads();
        // store tile (converted to tf32)
        {
            int kb = lhalf * 8;
            As[kb + 0][lm] = f2tf(ra0.x);
            As[kb + 1][lm] = f2tf(ra0.y);
            As[kb + 2][lm] = f2tf(ra0.z);
            As[kb + 3][lm] = f2tf(ra0.w);
            As[kb + 4][lm] = f2tf(ra1.x);
            As[kb + 5][lm] = f2tf(ra1.y);
            As[kb + 6][lm] = f2tf(ra1.z);
            As[kb + 7][lm] = f2tf(ra1.w);
            Bs[bk][bn + 0] = f2tf(rb0.x);
            Bs[bk][bn + 1] = f2tf(rb0.y);
            Bs[bk][bn + 2] = f2tf(rb0.z);
            Bs[bk][bn + 3] = f2tf(rb0.w);
            Bs[bk + 8][bn + 0] = f2tf(rb1.x);
            Bs[bk + 8][bn + 1] = f2tf(rb1.y);
            Bs[bk + 8][bn + 2] = f2tf(rb1.z);
            Bs[bk + 8][bn + 3] = f2tf(rb1.w);
        }
        __syncthreads();

        // prefetch next tile
        if (k0 + 16 < K) {
            if (aval) {
                ra0 = *(const float4*)(Ap + k0 + 16);
                ra1 = *(const float4*)(Ap + k0 + 20);
            }
            const float* bp = Bp + (size_t)(k0 + 16) * DH;
            rb0 = *(const float4*)(bp);
            rb1 = *(const float4*)(bp + (size_t)8 * DH);
        }

        // compute: 2 k8 steps
#pragma unroll
        for (int ks = 0; ks < 2; ks++) {
            const int kb = ks * 8;
            uint32_t af[4][4];
#pragma unroll
            for (int mi = 0; mi < 4; mi++) {
                int mb = wm * 64 + mi * 16;
                af[mi][0] = As[kb + c][mb + r];
                af[mi][1] = As[kb + c][mb + r + 8];
                af[mi][2] = As[kb + c + 4][mb + r];
                af[mi][3] = As[kb + c + 4][mb + r + 8];
            }
            uint32_t bf[4][2];
#pragma unroll
            for (int ni = 0; ni < 4; ni++) {
                int nb = wn * 32 + ni * 8;
                bf[ni][0] = Bs[kb + c][nb + r];
                bf[ni][1] = Bs[kb + c + 4][nb + r];
            }
#pragma unroll
            for (int mi = 0; mi < 4; mi++)
#pragma unroll
                for (int ni = 0; ni < 4; ni++) {
                    asm volatile(
                        "mma.sync.aligned.m16n8k8.row.col.f32.tf32.tf32.f32 "
                        "{%0,%1,%2,%3}, {%4,%5,%6,%7}, {%8,%9}, {%0,%1,%2,%3};"
                        : "+f"(acc[mi][ni][0]), "+f"(acc[mi][ni][1]),
                          "+f"(acc[mi][ni][2]), "+f"(acc[mi][ni][3])
                        : "r"(af[mi][0]), "r"(af[mi][1]), "r"(af[mi][2]), "r"(af[mi][3]),
                          "r"(bf[ni][0]), "r"(bf[ni][1]));
                }
        }
    }

    // epilogue
#pragma unroll
    for (int mi = 0; mi < 4; mi++) {
        int row = m0 + wm * 64 + mi * 16 + r;
#pragma unroll
        for (int ni = 0; ni < 4; ni++) {
            int col = n0 + wn * 32 + ni * 8 + c * 2;
            if (row < M)
                *(float2*)(C + (size_t)row * DH + col) =
                    make_float2(acc[mi][ni][0], acc[mi][ni][1]);
            if (row + 8 < M)
                *(float2*)(C + (size_t)(row + 8) * DH + col) =
                    make_float2(acc[mi][ni][2], acc[mi][ni][3]);
        }
    }
}

// ---------------- CSR gather aggregation ----------------
__global__ void __launch_bounds__(256) k_gather(
    const float* __restrict__ h, const float* __restrict__ bias,
    float* __restrict__ out, int doRelu)
{
    int n = blockIdx.x * 2 + threadIdx.y;
    if (n >= NN) return;
    int s = g_rowptr[n];
    int e = g_rowptr[n + 1];
    float dn = g_dinv[n];
    int c = threadIdx.x * 4;

    float4 v = *(const float4*)(h + (size_t)n * DH + c);
    float d2 = dn * dn;
    float4 acc = make_float4(v.x * d2, v.y * d2, v.z * d2, v.w * d2);

    int j = s;
    for (; j + 1 < e; j += 2) {
        int s0 = g_csrsrc[j];
        int s1 = g_csrsrc[j + 1];
        float c0 = g_dinv[s0] * dn;
        float c1 = g_dinv[s1] * dn;
        float4 v0 = *(const float4*)(h + (size_t)s0 * DH + c);
        float4 v1 = *(const float4*)(h + (size_t)s1 * DH + c);
        acc.x = fmaf(v0.x, c0, acc.x); acc.y = fmaf(v0.y, c0, acc.y);
        acc.z = fmaf(v0.z, c0, acc.z); acc.w = fmaf(v0.w, c0, acc.w);
        acc.x = fmaf(v1.x, c1, acc.x); acc.y = fmaf(v1.y, c1, acc.y);
        acc.z = fmaf(v1.z, c1, acc.z); acc.w = fmaf(v1.w, c1, acc.w);
    }
    if (j < e) {
        int s0 = g_csrsrc[j];
        float c0 = g_dinv[s0] * dn;
        float4 v0 = *(const float4*)(h + (size_t)s0 * DH + c);
        acc.x = fmaf(v0.x, c0, acc.x); acc.y = fmaf(v0.y, c0, acc.y);
        acc.z = fmaf(v0.z, c0, acc.z); acc.w = fmaf(v0.w, c0, acc.w);
    }

    float4 b = *(const float4*)(bias + c);
    acc.x += b.x; acc.y += b.y; acc.z += b.z; acc.w += b.w;
    if (doRelu) {
        acc.x = fmaxf(acc.x, 0.f); acc.y = fmaxf(acc.y, 0.f);
        acc.z = fmaxf(acc.z, 0.f); acc.w = fmaxf(acc.w, 0.f);
    }
    *(float4*)(out + (size_t)n * DH + c) = acc;
}

// ---------------- segment max ----------------
__device__ __forceinline__ int lower_bound_batch(const void* batch, int val) {
    int lo = 0, hi = NN;
    while (lo < hi) {
        int mid = (lo + hi) >> 1;
        if (idx_at(batch, mid) < val) lo = mid + 1; else hi = mid;
    }
    return lo;
}
__global__ void k_segmax(const void* __restrict__ batch) {
    int g = blockIdx.x;
    int c = threadIdx.x;
    int s = lower_bound_batch(batch, g);
    int e = lower_bound_batch(batch, g + 1);
    float m = 0.0f;
    for (int n = s; n < e; n++)
        m = fmaxf(m, g_agg[(size_t)n * DH + c]);
    g_pool[g * DH + c] = m;
}

// ---------------- FC head ----------------
__global__ void __launch_bounds__(256) k_head(
    const float* __restrict__ A, const float* __restrict__ B,
    const float* __restrict__ bias, float* __restrict__ C,
    int N, int K, int mode,
    const float* __restrict__ gamma, const float* __restrict__ beta)
{
    const int BK = 32, BN = 32;
    __shared__ float As[BK][64];
    __shared__ float Bs[BK][BN];

    int tid = threadIdx.x;
    int colBase = blockIdx.x * BN;
    int ty = tid >> 4, tx = tid & 15;

    float acc[4][2] = {{0.f, 0.f}, {0.f, 0.f}, {0.f, 0.f}, {0.f, 0.f}};

    for (int k0 = 0; k0 < K; k0 += BK) {
        __syncthreads();
#pragma unroll
        for (int l = 0; l < 8; l++) {
            int idx = tid * 8 + l;
            int m = idx >> 5, k = idx & 31;
            As[k][m] = A[(size_t)m * K + k0 + k];
        }
#pragma unroll
        for (int l = 0; l < 4; l++) {
            int idx = tid * 4 + l;
            int k = idx >> 5, n = idx & 31;
            int col = colBase + n;
            Bs[k][n] = (col < N) ? B[(size_t)(k0 + k) * N + col] : 0.f;
        }
        __syncthreads();
#pragma unroll
        for (int k = 0; k < BK; k++) {
            float ra2[4], rb2[2];
#pragma unroll
            for (int i = 0; i < 4; i++) ra2[i] = As[k][ty * 4 + i];
#pragma unroll
            for (int j = 0; j < 2; j++) rb2[j] = Bs[k][tx * 2 + j];
#pragma unroll
            for (int i = 0; i < 4; i++)
#pragma unroll
                for (int j = 0; j < 2; j++)
                    acc[i][j] = fmaf(ra2[i], rb2[j], acc[i][j]);
        }
    }

    const float bninv = rsqrtf(1.0f + 1e-5f);
#pragma unroll
    for (int i = 0; i < 4; i++) {
#pragma unroll
        for (int j = 0; j < 2; j++) {
            int row = ty * 4 + i;
            int col = colBase + tx * 2 + j;
            if (col < N) {
                float z = acc[i][j] + bias[col];
                if (mode == 0) {
                    z = fmaxf(z, 0.f);
                } else {
                    z = z * gamma[col] * bninv + beta[col];
                    z = 1.0f / (1.0f + expf(-z));
                }
                C[(size_t)row * N + col] = z;
            }
        }
    }
}

// ---------------- host ----------------
extern "C" void kernel_launch(void* const* d_in, const int* in_sizes, int n_in,
                              void* d_out, int out_size)
{
    const float* x     = (const float*)d_in[0];
    const void*  ei    = d_in[1];
    const void*  batch = d_in[2];
    const float* Wg1   = (const float*)d_in[3];
    const float* bg1   = (const float*)d_in[4];
    const float* Wg2   = (const float*)d_in[5];
    const float* bg2   = (const float*)d_in[6];
    const float* W1    = (const float*)d_in[7];
    const float* b1    = (const float*)d_in[8];
    const float* W2    = (const float*)d_in[9];
    const float* b2    = (const float*)d_in[10];
    const float* gamma = (const float*)d_in[11];
    const float* beta  = (const float*)d_in[12];
    float* out = (float*)d_out;

    float *p_h, *p_h2, *p_agg, *p_pool, *p_fc1;
    cudaGetSymbolAddress((void**)&p_h,    g_h);
    cudaGetSymbolAddress((void**)&p_h2,   g_h2);
    cudaGetSymbolAddress((void**)&p_agg,  g_agg);
    cudaGetSymbolAddress((void**)&p_pool, g_pool);
    cudaGetSymbolAddress((void**)&p_fc1,  g_fc1);

    k_detect<<<1, 1>>>(ei);

    k_zero_cnt<<<(NN + 255) / 256, 256>>>();
    k_deg<<<(NE + 255) / 256, 256>>>(ei);
    k_rsqrt<<<(NN + 255) / 256, 256>>>();
    k_scan<<<1, SCAN_T>>>();
    k_fill<<<(NE + 255) / 256, 256>>>(ei);

    dim3 gg((NN + 127) / 128, DH / 128);
    k_gemm_mma<<<gg, 256>>>(x, Wg1, p_h, NN, DIN);
    k_gather<<<(NN + 1) / 2, dim3(128, 2)>>>(p_h, bg1, p_agg, 1);

    k_gemm_mma<<<gg, 256>>>(p_agg, Wg2, p_h2, NN, DH);
    k_gather<<<(NN + 1) / 2, dim3(128, 2)>>>(p_h2, bg2, p_agg, 0);

    k_segmax<<<NG, DH>>>(batch);

    k_head<<<(DFC + 31) / 32, 256>>>(p_pool, W1, b1, p_fc1, DFC, DH, 0, nullptr, nullptr);
    k_head<<<(DOUT + 31) / 32, 256>>>(p_fc1, W2, b2, out, DOUT, DFC, 1, gamma, beta);
}

// round 5
// speedup vs baseline: 3.3740x; 1.2276x over previous
#include <cuda_runtime.h>
#include <math.h>
#include <stdint.h>

#define NN   20000
#define NE   320000
#define NG   64
#define DIN  1280
#define DH   512
#define DFC  1024
#define DOUT 5000

// ---------------- scratch ----------------
__device__ float g_h   [NN * DH];
__device__ float g_agg [NN * DH];
__device__ float g_h2  [NN * DH];
__device__ float g_dinv[NN];
__device__ int   g_cnt [NN];
__device__ int   g_rowptr[NN + 1];
__device__ int   g_cursor[NN];
__device__ int   g_csrsrc[NE];
__device__ float g_pool[NG * DH];
__device__ float g_fc1 [NG * DFC];
__device__ int   g_is64;

// ---------------- dtype detection ----------------
__global__ void k_detect(const void* ei) {
    const long long* p = (const long long*)ei;
    int ok = 1;
#pragma unroll
    for (int i = 0; i < 8; i++) {
        long long v = p[i];
        if (v < 0 || v >= NN) ok = 0;
    }
    g_is64 = ok;
}
__device__ __forceinline__ int idx_at(const void* p, long long i) {
    return g_is64 ? (int)((const long long*)p)[i] : ((const int*)p)[i];
}

// ---------------- degree / CSR ----------------
__global__ void k_zero_cnt() {
    int i = blockIdx.x * blockDim.x + threadIdx.x;
    if (i < NN) g_cnt[i] = 0;
}
__global__ void k_deg(const void* __restrict__ ei) {
    int e = blockIdx.x * blockDim.x + threadIdx.x;
    if (e < NE) atomicAdd(&g_cnt[idx_at(ei, (long long)NE + e)], 1);
}
__global__ void k_rsqrt() {
    int i = blockIdx.x * blockDim.x + threadIdx.x;
    if (i < NN) g_dinv[i] = rsqrtf((float)g_cnt[i] + 1.0f);
}

#define SCAN_T   1024
#define SCAN_CH  20
__global__ void __launch_bounds__(SCAN_T) k_scan() {
    __shared__ int s[SCAN_T];
    int tid = threadIdx.x;
    int base = tid * SCAN_CH;
    int local[SCAN_CH];
    int sum = 0;
#pragma unroll
    for (int i = 0; i < SCAN_CH; i++) {
        int idx = base + i;
        int v = (idx < NN) ? g_cnt[idx] : 0;
        local[i] = sum;
        sum += v;
    }
    s[tid] = sum;
    __syncthreads();
    for (int off = 1; off < SCAN_T; off <<= 1) {
        int v = (tid >= off) ? s[tid - off] : 0;
        __syncthreads();
        if (tid >= off) s[tid] += v;
        __syncthreads();
    }
    int pre = (tid > 0) ? s[tid - 1] : 0;
#pragma unroll
    for (int i = 0; i < SCAN_CH; i++) {
        int idx = base + i;
        if (idx < NN) {
            int v = pre + local[i];
            g_rowptr[idx] = v;
            g_cursor[idx] = v;
        }
    }
    if (tid == SCAN_T - 1) g_rowptr[NN] = NE;
}
__global__ void k_fill(const void* __restrict__ ei) {
    int e = blockIdx.x * blockDim.x + threadIdx.x;
    if (e < NE) {
        int src, dst;
        if (g_is64) {
            const long long* p = (const long long*)ei;
            src = (int)p[e]; dst = (int)p[NE + e];
        } else {
            const int* p = (const int*)ei;
            src = p[e]; dst = p[NE + e];
        }
        g_csrsrc[atomicAdd(&g_cursor[dst], 1)] = src;
    }
}

// ---------------- bf16 mma.sync GEMM: C[M,512] = A[M,K] @ B[K,512] ----------------
// BM=128, BN=128, BK=32. 256 threads = 8 warps (2x4). Warp tile 64x32.
// mma.m16n8k16 bf16, fragments via ldmatrix.
#define A_STR 40    // A smem row stride in halves (80B: conflict-free ldmatrix)
#define B_STR 136   // B smem row stride in halves (272B)

__device__ __forceinline__ uint32_t smem_u32(const void* p) {
    uint32_t a;
    asm("{ .reg .u64 t; cvta.to.shared.u64 t, %1; cvt.u32.u64 %0, t; }" : "=r"(a) : "l"(p));
    return a;
}
__device__ __forceinline__ uint32_t pack_bf16(float lo, float hi) {
    uint32_t r;
    asm("cvt.rn.bf16x2.f32 %0, %1, %2;" : "=r"(r) : "f"(hi), "f"(lo));
    return r;
}
__device__ __forceinline__ void ldsm_x4(uint32_t* r, uint32_t addr) {
    asm volatile("ldmatrix.sync.aligned.m8n8.x4.shared.b16 {%0,%1,%2,%3}, [%4];"
        : "=r"(r[0]), "=r"(r[1]), "=r"(r[2]), "=r"(r[3]) : "r"(addr));
}
__device__ __forceinline__ void ldsm_x2t(uint32_t* r, uint32_t addr) {
    asm volatile("ldmatrix.sync.aligned.m8n8.x2.trans.shared.b16 {%0,%1}, [%2];"
        : "=r"(r[0]), "=r"(r[1]) : "r"(addr));
}

__global__ void __launch_bounds__(256, 2) k_gemm_bf16(
    const float* __restrict__ A, const float* __restrict__ B,
    float* __restrict__ C, int M, int K)
{
    __shared__ __align__(16) uint16_t Asm[128 * A_STR];
    __shared__ __align__(16) uint16_t Bsm[32 * B_STR];

    const int tid  = threadIdx.x;
    const int wid  = tid >> 5;
    const int lane = tid & 31;
    const int wm   = wid >> 2;       // 0..1
    const int wn   = wid & 3;        // 0..3
    const int n0   = blockIdx.x * 128;   // fast dim = N columns (A reuse in L2)
    const int m0   = blockIdx.y * 128;

    // A loader: m = tid>>1, kh = (tid&1)*16 (16 k-floats per thread)
    const int alm = tid >> 1;
    const int akh = (tid & 1) * 16;
    const bool aval = (m0 + alm) < M;
    const float* Ap = A + (size_t)(m0 + alm) * K + akh;
    // B loader: k = tid>>3, nb = (tid&7)*16
    const int blk = tid >> 3;
    const int bnb = (tid & 7) * 16;
    const float* Bp = B + (size_t)blk * DH + n0 + bnb;

    const uint32_t aBase = smem_u32(Asm);
    const uint32_t bBase = smem_u32(Bsm);

    float acc[4][4][4];
#pragma unroll
    for (int mi = 0; mi < 4; mi++)
#pragma unroll
        for (int ni = 0; ni < 4; ni++)
#pragma unroll
            for (int q = 0; q < 4; q++) acc[mi][ni][q] = 0.0f;

    uint32_t ua[8], ub[8];

    // prefetch tile 0 (load f32, convert to packed bf16x2)
    {
        const float4* p = (const float4*)Ap;
        float4 t0, t1, t2, t3;
        if (aval) { t0 = p[0]; t1 = p[1]; t2 = p[2]; t3 = p[3]; }
        else { t0 = t1 = t2 = t3 = make_float4(0.f, 0.f, 0.f, 0.f); }
        ua[0] = pack_bf16(t0.x, t0.y); ua[1] = pack_bf16(t0.z, t0.w);
        ua[2] = pack_bf16(t1.x, t1.y); ua[3] = pack_bf16(t1.z, t1.w);
        ua[4] = pack_bf16(t2.x, t2.y); ua[5] = pack_bf16(t2.z, t2.w);
        ua[6] = pack_bf16(t3.x, t3.y); ua[7] = pack_bf16(t3.z, t3.w);
        const float4* q = (const float4*)Bp;
        float4 s0 = q[0], s1 = q[1], s2 = q[2], s3 = q[3];
        ub[0] = pack_bf16(s0.x, s0.y); ub[1] = pack_bf16(s0.z, s0.w);
        ub[2] = pack_bf16(s1.x, s1.y); ub[3] = pack_bf16(s1.z, s1.w);
        ub[4] = pack_bf16(s2.x, s2.y); ub[5] = pack_bf16(s2.z, s2.w);
        ub[6] = pack_bf16(s3.x, s3.y); ub[7] = pack_bf16(s3.z, s3.w);
    }

    const int lr15 = lane & 15;
    const int lk8  = (lane >> 4) << 3;

    for (int k0 = 0; k0 < K; k0 += 32) {
        __syncthreads();
        // STS (16B vector stores)
        *(uint4*)&Asm[alm * A_STR + akh]     = make_uint4(ua[0], ua[1], ua[2], ua[3]);
        *(uint4*)&Asm[alm * A_STR + akh + 8] = make_uint4(ua[4], ua[5], ua[6], ua[7]);
        *(uint4*)&Bsm[blk * B_STR + bnb]     = make_uint4(ub[0], ub[1], ub[2], ub[3]);
        *(uint4*)&Bsm[blk * B_STR + bnb + 8] = make_uint4(ub[4], ub[5], ub[6], ub[7]);
        __syncthreads();

        // prefetch next tile
        if (k0 + 32 < K) {
            const float4* p = (const float4*)(Ap + k0 + 32);
            float4 t0, t1, t2, t3;
            if (aval) { t0 = p[0]; t1 = p[1]; t2 = p[2]; t3 = p[3]; }
            else { t0 = t1 = t2 = t3 = make_float4(0.f, 0.f, 0.f, 0.f); }
            ua[0] = pack_bf16(t0.x, t0.y); ua[1] = pack_bf16(t0.z, t0.w);
            ua[2] = pack_bf16(t1.x, t1.y); ua[3] = pack_bf16(t1.z, t1.w);
            ua[4] = pack_bf16(t2.x, t2.y); ua[5] = pack_bf16(t2.z, t2.w);
            ua[6] = pack_bf16(t3.x, t3.y); ua[7] = pack_bf16(t3.z, t3.w);
            const float4* q = (const float4*)(Bp + (size_t)(k0 + 32) * DH);
            float4 s0 = q[0], s1 = q[1], s2 = q[2], s3 = q[3];
            ub[0] = pack_bf16(s0.x, s0.y); ub[1] = pack_bf16(s0.z, s0.w);
            ub[2] = pack_bf16(s1.x, s1.y); ub[3] = pack_bf16(s1.z, s1.w);
            ub[4] = pack_bf16(s2.x, s2.y); ub[5] = pack_bf16(s2.z, s2.w);
            ub[6] = pack_bf16(s3.x, s3.y); ub[7] = pack_bf16(s3.z, s3.w);
        }

        // compute: 2 k16 steps
#pragma unroll
        for (int ks = 0; ks < 2; ks++) {
            const int kb = ks * 16;
            uint32_t af[4][4], bfr[4][2];
#pragma unroll
            for (int mi = 0; mi < 4; mi++) {
                uint32_t ad = aBase +
                    (uint32_t)(((wm * 64 + mi * 16 + lr15) * A_STR + kb + lk8) * 2);
                ldsm_x4(af[mi], ad);
            }
#pragma unroll
            for (int ni = 0; ni < 4; ni++) {
                uint32_t bd = bBase +
                    (uint32_t)(((kb + lr15) * B_STR + wn * 32 + ni * 8) * 2);
                ldsm_x2t(bfr[ni], bd);
            }
#pragma unroll
            for (int mi = 0; mi < 4; mi++)
#pragma unroll
                for (int ni = 0; ni < 4; ni++) {
                    asm volatile(
                        "mma.sync.aligned.m16n8k16.row.col.f32.bf16.bf16.f32 "
                        "{%0,%1,%2,%3}, {%4,%5,%6,%7}, {%8,%9}, {%0,%1,%2,%3};"
                        : "+f"(acc[mi][ni][0]), "+f"(acc[mi][ni][1]),
                          "+f"(acc[mi][ni][2]), "+f"(acc[mi][ni][3])
                        : "r"(af[mi][0]), "r"(af[mi][1]), "r"(af[mi][2]), "r"(af[mi][3]),
                          "r"(bfr[ni][0]), "r"(bfr[ni][1]));
                }
        }
    }

    // epilogue
    const int r = lane >> 2;
    const int c = lane & 3;
#pragma unroll
    for (int mi = 0; mi < 4; mi++) {
        int row = m0 + wm * 64 + mi * 16 + r;
#pragma unroll
        for (int ni = 0; ni < 4; ni++) {
            int col = n0 + wn * 32 + ni * 8 + c * 2;
            if (row < M)
                *(float2*)(C + (size_t)row * DH + col) =
                    make_float2(acc[mi][ni][0], acc[mi][ni][1]);
            if (row + 8 < M)
                *(float2*)(C + (size_t)(row + 8) * DH + col) =
                    make_float2(acc[mi][ni][2], acc[mi][ni][3]);
        }
    }
}

// ---------------- CSR gather aggregation ----------------
__global__ void __launch_bounds__(256) k_gather(
    const float* __restrict__ h, const float* __restrict__ bias,
    float* __restrict__ out, int doRelu)
{
    int n = blockIdx.x * 2 + threadIdx.y;
    if (n >= NN) return;
    int s = g_rowptr[n];
    int e = g_rowptr[n + 1];
    float dn = g_dinv[n];
    int c = threadIdx.x * 4;

    float4 v = *(const float4*)(h + (size_t)n * DH + c);
    float d2 = dn * dn;
    float4 acc = make_float4(v.x * d2, v.y * d2, v.z * d2, v.w * d2);

    int j = s;
    for (; j + 1 < e; j += 2) {
        int s0 = g_csrsrc[j];
        int s1 = g_csrsrc[j + 1];
        float c0 = g_dinv[s0] * dn;
        float c1 = g_dinv[s1] * dn;
        float4 v0 = *(const float4*)(h + (size_t)s0 * DH + c);
        float4 v1 = *(const float4*)(h + (size_t)s1 * DH + c);
        acc.x = fmaf(v0.x, c0, acc.x); acc.y = fmaf(v0.y, c0, acc.y);
        acc.z = fmaf(v0.z, c0, acc.z); acc.w = fmaf(v0.w, c0, acc.w);
        acc.x = fmaf(v1.x, c1, acc.x); acc.y = fmaf(v1.y, c1, acc.y);
        acc.z = fmaf(v1.z, c1, acc.z); acc.w = fmaf(v1.w, c1, acc.w);
    }
    if (j < e) {
        int s0 = g_csrsrc[j];
        float c0 = g_dinv[s0] * dn;
        float4 v0 = *(const float4*)(h + (size_t)s0 * DH + c);
        acc.x = fmaf(v0.x, c0, acc.x); acc.y = fmaf(v0.y, c0, acc.y);
        acc.z = fmaf(v0.z, c0, acc.z); acc.w = fmaf(v0.w, c0, acc.w);
    }

    float4 b = *(const float4*)(bias + c);
    acc.x += b.x; acc.y += b.y; acc.z += b.z; acc.w += b.w;
    if (doRelu) {
        acc.x = fmaxf(acc.x, 0.f); acc.y = fmaxf(acc.y, 0.f);
        acc.z = fmaxf(acc.z, 0.f); acc.w = fmaxf(acc.w, 0.f);
    }
    *(float4*)(out + (size_t)n * DH + c) = acc;
}

// ---------------- segment max ----------------
__device__ __forceinline__ int lower_bound_batch(const void* batch, int val) {
    int lo = 0, hi = NN;
    while (lo < hi) {
        int mid = (lo + hi) >> 1;
        if (idx_at(batch, mid) < val) lo = mid + 1; else hi = mid;
    }
    return lo;
}
__global__ void k_segmax(const void* __restrict__ batch) {
    int g = blockIdx.x;
    int c = threadIdx.x;
    int s = lower_bound_batch(batch, g);
    int e = lower_bound_batch(batch, g + 1);
    float m = 0.0f;
    for (int n = s; n < e; n++)
        m = fmaxf(m, g_agg[(size_t)n * DH + c]);
    g_pool[g * DH + c] = m;
}

// ---------------- FC head ----------------
__global__ void __launch_bounds__(256) k_head(
    const float* __restrict__ A, const float* __restrict__ B,
    const float* __restrict__ bias, float* __restrict__ C,
    int N, int K, int mode,
    const float* __restrict__ gamma, const float* __restrict__ beta)
{
    const int BK = 32, BN = 32;
    __shared__ float As[BK][64];
    __shared__ float Bs[BK][BN];

    int tid = threadIdx.x;
    int colBase = blockIdx.x * BN;
    int ty = tid >> 4, tx = tid & 15;

    float acc[4][2] = {{0.f, 0.f}, {0.f, 0.f}, {0.f, 0.f}, {0.f, 0.f}};

    for (int k0 = 0; k0 < K; k0 += BK) {
        __syncthreads();
#pragma unroll
        for (int l = 0; l < 8; l++) {
            int idx = tid * 8 + l;
            int m = idx >> 5, k = idx & 31;
            As[k][m] = A[(size_t)m * K + k0 + k];
        }
#pragma unroll
        for (int l = 0; l < 4; l++) {
            int idx = tid * 4 + l;
            int k = idx >> 5, n = idx & 31;
            int col = colBase + n;
            Bs[k][n] = (col < N) ? B[(size_t)(k0 + k) * N + col] : 0.f;
        }
        __syncthreads();
#pragma unroll
        for (int k = 0; k < BK; k++) {
            float ra2[4], rb2[2];
#pragma unroll
            for (int i = 0; i < 4; i++) ra2[i] = As[k][ty * 4 + i];
#pragma unroll
            for (int j = 0; j < 2; j++) rb2[j] = Bs[k][tx * 2 + j];
#pragma unroll
            for (int i = 0; i < 4; i++)
#pragma unroll
                for (int j = 0; j < 2; j++)
                    acc[i][j] = fmaf(ra2[i], rb2[j], acc[i][j]);
        }
    }

    const float bninv = rsqrtf(1.0f + 1e-5f);
#pragma unroll
    for (int i = 0; i < 4; i++) {
#pragma unroll
        for (int j = 0; j < 2; j++) {
            int row = ty * 4 + i;
            int col = colBase + tx * 2 + j;
            if (col < N) {
                float z = acc[i][j] + bias[col];
                if (mode == 0) {
                    z = fmaxf(z, 0.f);
                } else {
                    z = z * gamma[col] * bninv + beta[col];
                    z = 1.0f / (1.0f + expf(-z));
                }
                C[(size_t)row * N + col] = z;
            }
        }
    }
}

// ---------------- host ----------------
extern "C" void kernel_launch(void* const* d_in, const int* in_sizes, int n_in,
                              void* d_out, int out_size)
{
    const float* x     = (const float*)d_in[0];
    const void*  ei    = d_in[1];
    const void*  batch = d_in[2];
    const float* Wg1   = (const float*)d_in[3];
    const float* bg1   = (const float*)d_in[4];
    const float* Wg2   = (const float*)d_in[5];
    const float* bg2   = (const float*)d_in[6];
    const float* W1    = (const float*)d_in[7];
    const float* b1    = (const float*)d_in[8];
    const float* W2    = (const float*)d_in[9];
    const float* b2    = (const float*)d_in[10];
    const float* gamma = (const float*)d_in[11];
    const float* beta  = (const float*)d_in[12];
    float* out = (float*)d_out;

    float *p_h, *p_h2, *p_agg, *p_pool, *p_fc1;
    cudaGetSymbolAddress((void**)&p_h,    g_h);
    cudaGetSymbolAddress((void**)&p_h2,   g_h2);
    cudaGetSymbolAddress((void**)&p_agg,  g_agg);
    cudaGetSymbolAddress((void**)&p_pool, g_pool);
    cudaGetSymbolAddress((void**)&p_fc1,  g_fc1);

    k_detect<<<1, 1>>>(ei);

    k_zero_cnt<<<(NN + 255) / 256, 256>>>();
    k_deg<<<(NE + 255) / 256, 256>>>(ei);
    k_rsqrt<<<(NN + 255) / 256, 256>>>();
    k_scan<<<1, SCAN_T>>>();
    k_fill<<<(NE + 255) / 256, 256>>>(ei);

    dim3 gg(DH / 128, (NN + 127) / 128);  // x = N-cols (fast) -> A reuse in L2
    k_gemm_bf16<<<gg, 256>>>(x, Wg1, p_h, NN, DIN);
    k_gather<<<(NN + 1) / 2, dim3(128, 2)>>>(p_h, bg1, p_agg, 1);

    k_gemm_bf16<<<gg, 256>>>(p_agg, Wg2, p_h2, NN, DH);
    k_gather<<<(NN + 1) / 2, dim3(128, 2)>>>(p_h2, bg2, p_agg, 0);

    k_segmax<<<NG, DH>>>(batch);

    k_head<<<(DFC + 31) / 32, 256>>>(p_pool, W1, b1, p_fc1, DFC, DH, 0, nullptr, nullptr);
    k_head<<<(DOUT + 31) / 32, 256>>>(p_fc1, W2, b2, out, DOUT, DFC, 1, gamma, beta);
}

// round 6
// speedup vs baseline: 3.6692x; 1.0875x over previous
#include <cuda_runtime.h>
#include <math.h>
#include <stdint.h>

#define NN   20000
#define NE   320000
#define NG   64
#define DIN  1280
#define DH   512
#define DFC  1024
#define DOUT 5000

// ---------------- scratch ----------------
__device__ uint16_t g_hbf  [NN * DH];   // layer-1 GEMM out (bf16)
__device__ uint16_t g_aggbf[NN * DH];   // gather-1 out = GEMM2 A (bf16)
__device__ uint16_t g_h2bf [NN * DH];   // layer-2 GEMM out (bf16)
__device__ float    g_agg  [NN * DH];   // gather-2 out (fp32)
__device__ float    g_dinv [NN];
__device__ int      g_cnt  [NN];
__device__ int      g_rowptr[NN + 1];
__device__ int      g_cursor[NN];
__device__ int      g_csrsrc[NE];
__device__ float    g_pool[NG * DH];
__device__ float    g_fc1 [NG * DFC];
__device__ int      g_is64;

// ---------------- helpers ----------------
__device__ __forceinline__ uint32_t smem_u32(const void* p) {
    uint32_t a;
    asm("{ .reg .u64 t; cvta.to.shared.u64 t, %1; cvt.u32.u64 %0, t; }" : "=r"(a) : "l"(p));
    return a;
}
__device__ __forceinline__ uint32_t pack_bf16(float lo, float hi) {
    uint32_t r;
    asm("cvt.rn.bf16x2.f32 %0, %1, %2;" : "=r"(r) : "f"(hi), "f"(lo));
    return r;
}
__device__ __forceinline__ float bf_lo(uint32_t u) { return __uint_as_float(u << 16); }
__device__ __forceinline__ float bf_hi(uint32_t u) { return __uint_as_float(u & 0xFFFF0000u); }

__device__ __forceinline__ void ldsm_x4(uint32_t* r, uint32_t addr) {
    asm volatile("ldmatrix.sync.aligned.m8n8.x4.shared.b16 {%0,%1,%2,%3}, [%4];"
        : "=r"(r[0]), "=r"(r[1]), "=r"(r[2]), "=r"(r[3]) : "r"(addr));
}
__device__ __forceinline__ void ldsm_x2t(uint32_t* r, uint32_t addr) {
    asm volatile("ldmatrix.sync.aligned.m8n8.x2.trans.shared.b16 {%0,%1}, [%2];"
        : "=r"(r[0]), "=r"(r[1]) : "r"(addr));
}

// ---------------- dtype detection ----------------
__global__ void k_detect(const void* ei) {
    const long long* p = (const long long*)ei;
    int ok = 1;
#pragma unroll
    for (int i = 0; i < 8; i++) {
        long long v = p[i];
        if (v < 0 || v >= NN) ok = 0;
    }
    g_is64 = ok;
}
__device__ __forceinline__ int idx_at(const void* p, long long i) {
    return g_is64 ? (int)((const long long*)p)[i] : ((const int*)p)[i];
}

// ---------------- degree / CSR ----------------
__global__ void k_zero_cnt() {
    int i = blockIdx.x * blockDim.x + threadIdx.x;
    if (i < NN) g_cnt[i] = 0;
}
__global__ void k_deg(const void* __restrict__ ei) {
    int e = blockIdx.x * blockDim.x + threadIdx.x;
    if (e < NE) atomicAdd(&g_cnt[idx_at(ei, (long long)NE + e)], 1);
}
__global__ void k_rsqrt() {
    int i = blockIdx.x * blockDim.x + threadIdx.x;
    if (i < NN) g_dinv[i] = rsqrtf((float)g_cnt[i] + 1.0f);
}

#define SCAN_T   1024
#define SCAN_CH  20
__global__ void __launch_bounds__(SCAN_T) k_scan() {
    __shared__ int s[SCAN_T];
    int tid = threadIdx.x;
    int base = tid * SCAN_CH;
    int local[SCAN_CH];
    int sum = 0;
#pragma unroll
    for (int i = 0; i < SCAN_CH; i++) {
        int idx = base + i;
        int v = (idx < NN) ? g_cnt[idx] : 0;
        local[i] = sum;
        sum += v;
    }
    s[tid] = sum;
    __syncthreads();
    for (int off = 1; off < SCAN_T; off <<= 1) {
        int v = (tid >= off) ? s[tid - off] : 0;
        __syncthreads();
        if (tid >= off) s[tid] += v;
        __syncthreads();
    }
    int pre = (tid > 0) ? s[tid - 1] : 0;
#pragma unroll
    for (int i = 0; i < SCAN_CH; i++) {
        int idx = base + i;
        if (idx < NN) {
            int v = pre + local[i];
            g_rowptr[idx] = v;
            g_cursor[idx] = v;
        }
    }
    if (tid == SCAN_T - 1) g_rowptr[NN] = NE;
}
__global__ void k_fill(const void* __restrict__ ei) {
    int e = blockIdx.x * blockDim.x + threadIdx.x;
    if (e < NE) {
        int src, dst;
        if (g_is64) {
            const long long* p = (const long long*)ei;
            src = (int)p[e]; dst = (int)p[NE + e];
        } else {
            const int* p = (const int*)ei;
            src = p[e]; dst = p[NE + e];
        }
        g_csrsrc[atomicAdd(&g_cursor[dst], 1)] = src;
    }
}

// ---------------- bf16 mma GEMM: C[M,512] = A[M,K] @ B[K,512] ----------------
// BM=128, BN=128, BK=32. 256 thr = 8 warps (2x4), warp tile 64x32.
// ABF: A stored bf16; else f32 (converted on load). C always written bf16.
#define A_STR 40
#define B_STR 136

template <int ABF>
__global__ void __launch_bounds__(256, 2) k_gemm_bf16(
    const void* __restrict__ Av, const float* __restrict__ B,
    uint16_t* __restrict__ Cb, int M, int K)
{
    __shared__ __align__(16) uint16_t Asm[128 * A_STR];
    __shared__ __align__(16) uint16_t Bsm[32 * B_STR];

    const int tid  = threadIdx.x;
    const int wid  = tid >> 5;
    const int lane = tid & 31;
    const int wm   = wid >> 2;
    const int wn   = wid & 3;
    const int n0   = blockIdx.x * 128;
    const int m0   = blockIdx.y * 128;

    const int alm = tid >> 1;
    const int akh = (tid & 1) * 16;
    const bool aval = (m0 + alm) < M;
    const int blk = tid >> 3;
    const int bnb = (tid & 7) * 16;
    const float* Bp = B + (size_t)blk * DH + n0 + bnb;

    const uint32_t aBase = smem_u32(Asm);
    const uint32_t bBase = smem_u32(Bsm);

    float acc[4][4][4];
#pragma unroll
    for (int mi = 0; mi < 4; mi++)
#pragma unroll
        for (int ni = 0; ni < 4; ni++)
#pragma unroll
            for (int q = 0; q < 4; q++) acc[mi][ni][q] = 0.0f;

    uint32_t ua[8], ub[8];

    const float*    Apf = (const float*)Av + (size_t)(m0 + alm) * K + akh;
    const uint16_t* Aph = (const uint16_t*)Av + (size_t)(m0 + alm) * K + akh;

    // prefetch tile 0
    if (ABF) {
        uint4 p0, p1;
        if (aval) { p0 = *(const uint4*)Aph; p1 = *(const uint4*)(Aph + 8); }
        else { p0 = make_uint4(0,0,0,0); p1 = p0; }
        ua[0]=p0.x; ua[1]=p0.y; ua[2]=p0.z; ua[3]=p0.w;
        ua[4]=p1.x; ua[5]=p1.y; ua[6]=p1.z; ua[7]=p1.w;
    } else {
        const float4* p = (const float4*)Apf;
        float4 t0, t1, t2, t3;
        if (aval) { t0 = p[0]; t1 = p[1]; t2 = p[2]; t3 = p[3]; }
        else { t0 = t1 = t2 = t3 = make_float4(0.f,0.f,0.f,0.f); }
        ua[0] = pack_bf16(t0.x, t0.y); ua[1] = pack_bf16(t0.z, t0.w);
        ua[2] = pack_bf16(t1.x, t1.y); ua[3] = pack_bf16(t1.z, t1.w);
        ua[4] = pack_bf16(t2.x, t2.y); ua[5] = pack_bf16(t2.z, t2.w);
        ua[6] = pack_bf16(t3.x, t3.y); ua[7] = pack_bf16(t3.z, t3.w);
    }
    {
        const float4* q = (const float4*)Bp;
        float4 s0 = q[0], s1 = q[1], s2 = q[2], s3 = q[3];
        ub[0] = pack_bf16(s0.x, s0.y); ub[1] = pack_bf16(s0.z, s0.w);
        ub[2] = pack_bf16(s1.x, s1.y); ub[3] = pack_bf16(s1.z, s1.w);
        ub[4] = pack_bf16(s2.x, s2.y); ub[5] = pack_bf16(s2.z, s2.w);
        ub[6] = pack_bf16(s3.x, s3.y); ub[7] = pack_bf16(s3.z, s3.w);
    }

    const int lr15 = lane & 15;
    const int lk8  = (lane >> 4) << 3;

    for (int k0 = 0; k0 < K; k0 += 32) {
        __syncthreads();
        *(uint4*)&Asm[alm * A_STR + akh]     = make_uint4(ua[0], ua[1], ua[2], ua[3]);
        *(uint4*)&Asm[alm * A_STR + akh + 8] = make_uint4(ua[4], ua[5], ua[6], ua[7]);
        *(uint4*)&Bsm[blk * B_STR + bnb]     = make_uint4(ub[0], ub[1], ub[2], ub[3]);
        *(uint4*)&Bsm[blk * B_STR + bnb + 8] = make_uint4(ub[4], ub[5], ub[6], ub[7]);
        __syncthreads();

        if (k0 + 32 < K) {
            if (ABF) {
                uint4 p0, p1;
                if (aval) {
                    p0 = *(const uint4*)(Aph + k0 + 32);
                    p1 = *(const uint4*)(Aph + k0 + 40);
                } else { p0 = make_uint4(0,0,0,0); p1 = p0; }
                ua[0]=p0.x; ua[1]=p0.y; ua[2]=p0.z; ua[3]=p0.w;
                ua[4]=p1.x; ua[5]=p1.y; ua[6]=p1.z; ua[7]=p1.w;
            } else {
                const float4* p = (const float4*)(Apf + k0 + 32);
                float4 t0, t1, t2, t3;
                if (aval) { t0 = p[0]; t1 = p[1]; t2 = p[2]; t3 = p[3]; }
                else { t0 = t1 = t2 = t3 = make_float4(0.f,0.f,0.f,0.f); }
                ua[0] = pack_bf16(t0.x, t0.y); ua[1] = pack_bf16(t0.z, t0.w);
                ua[2] = pack_bf16(t1.x, t1.y); ua[3] = pack_bf16(t1.z, t1.w);
                ua[4] = pack_bf16(t2.x, t2.y); ua[5] = pack_bf16(t2.z, t2.w);
                ua[6] = pack_bf16(t3.x, t3.y); ua[7] = pack_bf16(t3.z, t3.w);
            }
            const float4* q = (const float4*)(Bp + (size_t)(k0 + 32) * DH);
            float4 s0 = q[0], s1 = q[1], s2 = q[2], s3 = q[3];
            ub[0] = pack_bf16(s0.x, s0.y); ub[1] = pack_bf16(s0.z, s0.w);
            ub[2] = pack_bf16(s1.x, s1.y); ub[3] = pack_bf16(s1.z, s1.w);
            ub[4] = pack_bf16(s2.x, s2.y); ub[5] = pack_bf16(s2.z, s2.w);
            ub[6] = pack_bf16(s3.x, s3.y); ub[7] = pack_bf16(s3.z, s3.w);
        }

#pragma unroll
        for (int ks = 0; ks < 2; ks++) {
            const int kb = ks * 16;
            uint32_t af[4][4], bfr[4][2];
#pragma unroll
            for (int mi = 0; mi < 4; mi++) {
                uint32_t ad = aBase +
                    (uint32_t)(((wm * 64 + mi * 16 + lr15) * A_STR + kb + lk8) * 2);
                ldsm_x4(af[mi], ad);
            }
#pragma unroll
            for (int ni = 0; ni < 4; ni++) {
                uint32_t bd = bBase +
                    (uint32_t)(((kb + lr15) * B_STR + wn * 32 + ni * 8) * 2);
                ldsm_x2t(bfr[ni], bd);
            }
#pragma unroll
            for (int mi = 0; mi < 4; mi++)
#pragma unroll
                for (int ni = 0; ni < 4; ni++) {
                    asm volatile(
                        "mma.sync.aligned.m16n8k16.row.col.f32.bf16.bf16.f32 "
                        "{%0,%1,%2,%3}, {%4,%5,%6,%7}, {%8,%9}, {%0,%1,%2,%3};"
                        : "+f"(acc[mi][ni][0]), "+f"(acc[mi][ni][1]),
                          "+f"(acc[mi][ni][2]), "+f"(acc[mi][ni][3])
                        : "r"(af[mi][0]), "r"(af[mi][1]), "r"(af[mi][2]), "r"(af[mi][3]),
                          "r"(bfr[ni][0]), "r"(bfr[ni][1]));
                }
        }
    }

    // epilogue: pack fp32 acc -> bf16 pairs
    const int r = lane >> 2;
    const int c = lane & 3;
#pragma unroll
    for (int mi = 0; mi < 4; mi++) {
        int row = m0 + wm * 64 + mi * 16 + r;
#pragma unroll
        for (int ni = 0; ni < 4; ni++) {
            int col = n0 + wn * 32 + ni * 8 + c * 2;
            if (row < M)
                *(uint32_t*)(Cb + (size_t)row * DH + col) =
                    pack_bf16(acc[mi][ni][0], acc[mi][ni][1]);
            if (row + 8 < M)
                *(uint32_t*)(Cb + (size_t)(row + 8) * DH + col) =
                    pack_bf16(acc[mi][ni][2], acc[mi][ni][3]);
        }
    }
}

// ---------------- CSR gather (bf16 in) ----------------
// OBF=1: out bf16 + relu ; OBF=0: out fp32, no relu.
template <int OBF>
__global__ void __launch_bounds__(256) k_gather(
    const uint16_t* __restrict__ h, const float* __restrict__ bias,
    void* __restrict__ outv)
{
    int n = blockIdx.x * 2 + threadIdx.y;
    if (n >= NN) return;
    int s = g_rowptr[n];
    int e = g_rowptr[n + 1];
    float dn = g_dinv[n];
    int c = threadIdx.x * 4;

    // self-loop
    uint2 u = *(const uint2*)(h + (size_t)n * DH + c);
    float d2 = dn * dn;
    float a0 = bf_lo(u.x) * d2, a1 = bf_hi(u.x) * d2;
    float a2 = bf_lo(u.y) * d2, a3 = bf_hi(u.y) * d2;

    int j = s;
    for (; j + 3 < e; j += 4) {
        int s0 = g_csrsrc[j],     s1 = g_csrsrc[j + 1];
        int s2 = g_csrsrc[j + 2], s3 = g_csrsrc[j + 3];
        float c0 = g_dinv[s0] * dn, c1 = g_dinv[s1] * dn;
        float c2 = g_dinv[s2] * dn, c3 = g_dinv[s3] * dn;
        uint2 u0 = *(const uint2*)(h + (size_t)s0 * DH + c);
        uint2 u1 = *(const uint2*)(h + (size_t)s1 * DH + c);
        uint2 u2 = *(const uint2*)(h + (size_t)s2 * DH + c);
        uint2 u3 = *(const uint2*)(h + (size_t)s3 * DH + c);
        a0 = fmaf(bf_lo(u0.x), c0, a0); a1 = fmaf(bf_hi(u0.x), c0, a1);
        a2 = fmaf(bf_lo(u0.y), c0, a2); a3 = fmaf(bf_hi(u0.y), c0, a3);
        a0 = fmaf(bf_lo(u1.x), c1, a0); a1 = fmaf(bf_hi(u1.x), c1, a1);
        a2 = fmaf(bf_lo(u1.y), c1, a2); a3 = fmaf(bf_hi(u1.y), c1, a3);
        a0 = fmaf(bf_lo(u2.x), c2, a0); a1 = fmaf(bf_hi(u2.x), c2, a1);
        a2 = fmaf(bf_lo(u2.y), c2, a2); a3 = fmaf(bf_hi(u2.y), c2, a3);
        a0 = fmaf(bf_lo(u3.x), c3, a0); a1 = fmaf(bf_hi(u3.x), c3, a1);
        a2 = fmaf(bf_lo(u3.y), c3, a2); a3 = fmaf(bf_hi(u3.y), c3, a3);
    }
    for (; j < e; j++) {
        int s0 = g_csrsrc[j];
        float c0 = g_dinv[s0] * dn;
        uint2 u0 = *(const uint2*)(h + (size_t)s0 * DH + c);
        a0 = fmaf(bf_lo(u0.x), c0, a0); a1 = fmaf(bf_hi(u0.x), c0, a1);
        a2 = fmaf(bf_lo(u0.y), c0, a2); a3 = fmaf(bf_hi(u0.y), c0, a3);
    }

    float4 b = *(const float4*)(bias + c);
    a0 += b.x; a1 += b.y; a2 += b.z; a3 += b.w;
    if (OBF) {
        a0 = fmaxf(a0, 0.f); a1 = fmaxf(a1, 0.f);
        a2 = fmaxf(a2, 0.f); a3 = fmaxf(a3, 0.f);
        uint16_t* ob = (uint16_t*)outv;
        *(uint2*)(ob + (size_t)n * DH + c) =
            make_uint2(pack_bf16(a0, a1), pack_bf16(a2, a3));
    } else {
        float* of = (float*)outv;
        *(float4*)(of + (size_t)n * DH + c) = make_float4(a0, a1, a2, a3);
    }
}

// ---------------- segment max ----------------
__device__ __forceinline__ int lower_bound_batch(const void* batch, int val) {
    int lo = 0, hi = NN;
    while (lo < hi) {
        int mid = (lo + hi) >> 1;
        if (idx_at(batch, mid) < val) lo = mid + 1; else hi = mid;
    }
    return lo;
}
__global__ void k_segmax(const void* __restrict__ batch) {
    int g = blockIdx.x;
    int c = threadIdx.x;
    int s = lower_bound_batch(batch, g);
    int e = lower_bound_batch(batch, g + 1);
    float m = 0.0f;
    for (int n = s; n < e; n++)
        m = fmaxf(m, g_agg[(size_t)n * DH + c]);
    g_pool[g * DH + c] = m;
}

// ---------------- FC head ----------------
__global__ void __launch_bounds__(256) k_head(
    const float* __restrict__ A, const float* __restrict__ B,
    const float* __restrict__ bias, float* __restrict__ C,
    int N, int K, int mode,
    const float* __restrict__ gamma, const float* __restrict__ beta)
{
    const int BK = 32, BN = 32;
    __shared__ float As[BK][64];
    __shared__ float Bs[BK][BN];

    int tid = threadIdx.x;
    int colBase = blockIdx.x * BN;
    int ty = tid >> 4, tx = tid & 15;

    float acc[4][2] = {{0.f, 0.f}, {0.f, 0.f}, {0.f, 0.f}, {0.f, 0.f}};

    for (int k0 = 0; k0 < K; k0 += BK) {
        __syncthreads();
#pragma unroll
        for (int l = 0; l < 8; l++) {
            int idx = tid * 8 + l;
            int m = idx >> 5, k = idx & 31;
            As[k][m] = A[(size_t)m * K + k0 + k];
        }
#pragma unroll
        for (int l = 0; l < 4; l++) {
            int idx = tid * 4 + l;
            int k = idx >> 5, n = idx & 31;
            int col = colBase + n;
            Bs[k][n] = (col < N) ? B[(size_t)(k0 + k) * N + col] : 0.f;
        }
        __syncthreads();
#pragma unroll
        for (int k = 0; k < BK; k++) {
            float ra2[4], rb2[2];
#pragma unroll
            for (int i = 0; i < 4; i++) ra2[i] = As[k][ty * 4 + i];
#pragma unroll
            for (int j = 0; j < 2; j++) rb2[j] = Bs[k][tx * 2 + j];
#pragma unroll
            for (int i = 0; i < 4; i++)
#pragma unroll
                for (int j = 0; j < 2; j++)
                    acc[i][j] = fmaf(ra2[i], rb2[j], acc[i][j]);
        }
    }

    const float bninv = rsqrtf(1.0f + 1e-5f);
#pragma unroll
    for (int i = 0; i < 4; i++) {
#pragma unroll
        for (int j = 0; j < 2; j++) {
            int row = ty * 4 + i;
            int col = colBase + tx * 2 + j;
            if (col < N) {
                float z = acc[i][j] + bias[col];
                if (mode == 0) {
                    z = fmaxf(z, 0.f);
                } else {
                    z = z * gamma[col] * bninv + beta[col];
                    z = 1.0f / (1.0f + expf(-z));
                }
                C[(size_t)row * N + col] = z;
            }
        }
    }
}

// ---------------- host ----------------
extern "C" void kernel_launch(void* const* d_in, const int* in_sizes, int n_in,
                              void* d_out, int out_size)
{
    const float* x     = (const float*)d_in[0];
    const void*  ei    = d_in[1];
    const void*  batch = d_in[2];
    const float* Wg1   = (const float*)d_in[3];
    const float* bg1   = (const float*)d_in[4];
    const float* Wg2   = (const float*)d_in[5];
    const float* bg2   = (const float*)d_in[6];
    const float* W1    = (const float*)d_in[7];
    const float* b1    = (const float*)d_in[8];
    const float* W2    = (const float*)d_in[9];
    const float* b2    = (const float*)d_in[10];
    const float* gamma = (const float*)d_in[11];
    const float* beta  = (const float*)d_in[12];
    float* out = (float*)d_out;

    uint16_t *p_hbf, *p_aggbf, *p_h2bf;
    float *p_agg, *p_pool, *p_fc1;
    cudaGetSymbolAddress((void**)&p_hbf,   g_hbf);
    cudaGetSymbolAddress((void**)&p_aggbf, g_aggbf);
    cudaGetSymbolAddress((void**)&p_h2bf,  g_h2bf);
    cudaGetSymbolAddress((void**)&p_agg,   g_agg);
    cudaGetSymbolAddress((void**)&p_pool,  g_pool);
    cudaGetSymbolAddress((void**)&p_fc1,   g_fc1);

    k_detect<<<1, 1>>>(ei);

    k_zero_cnt<<<(NN + 255) / 256, 256>>>();
    k_deg<<<(NE + 255) / 256, 256>>>(ei);
    k_rsqrt<<<(NN + 255) / 256, 256>>>();
    k_scan<<<1, SCAN_T>>>();
    k_fill<<<(NE + 255) / 256, 256>>>(ei);

    dim3 gg(DH / 128, (NN + 127) / 128);
    k_gemm_bf16<0><<<gg, 256>>>(x, Wg1, p_hbf, NN, DIN);
    k_gather<1><<<(NN + 1) / 2, dim3(128, 2)>>>(p_hbf, bg1, p_aggbf);

    k_gemm_bf16<1><<<gg, 256>>>(p_aggbf, Wg2, p_h2bf, NN, DH);
    k_gather<0><<<(NN + 1) / 2, dim3(128, 2)>>>(p_h2bf, bg2, p_agg);

    k_segmax<<<NG, DH>>>(batch);

    k_head<<<(DFC + 31) / 32, 256>>>(p_pool, W1, b1, p_fc1, DFC, DH, 0, nullptr, nullptr);
    k_head<<<(DOUT + 31) / 32, 256>>>(p_fc1, W2, b2, out, DOUT, DFC, 1, gamma, beta);
}

// round 7
// speedup vs baseline: 4.7293x; 1.2889x over previous
#include <cuda_runtime.h>
#include <math.h>
#include <stdint.h>

#define NN   20000
#define NE   320000
#define NG   64
#define DIN  1280
#define DH   512
#define DFC  1024
#define DOUT 5000

// ---------------- scratch ----------------
__device__ uint16_t g_xbf  [NN * DIN];  // x in bf16
__device__ uint16_t g_w1bf [DIN * DH];  // Wg1 bf16
__device__ uint16_t g_w2bf [DH * DH];   // Wg2 bf16
__device__ uint16_t g_hbf  [NN * DH];   // layer-1 GEMM out (bf16)
__device__ uint16_t g_aggbf[NN * DH];   // gather-1 out = GEMM2 A (bf16)
__device__ uint16_t g_h2bf [NN * DH];   // layer-2 GEMM out (bf16)
__device__ float    g_agg  [NN * DH];   // gather-2 out (fp32)
__device__ float    g_dinv [NN];
__device__ int      g_cnt  [NN];
__device__ int      g_rowptr[NN + 1];
__device__ int      g_cursor[NN];
__device__ int      g_csrsrc[NE];
__device__ float    g_pool[NG * DH];
__device__ float    g_fc1 [NG * DFC];
__device__ int      g_is64;

// ---------------- helpers ----------------
__device__ __forceinline__ uint32_t smem_u32(const void* p) {
    uint32_t a;
    asm("{ .reg .u64 t; cvta.to.shared.u64 t, %1; cvt.u32.u64 %0, t; }" : "=r"(a) : "l"(p));
    return a;
}
__device__ __forceinline__ uint32_t pack_bf16(float lo, float hi) {
    uint32_t r;
    asm("cvt.rn.bf16x2.f32 %0, %1, %2;" : "=r"(r) : "f"(hi), "f"(lo));
    return r;
}
__device__ __forceinline__ float bf_lo(uint32_t u) { return __uint_as_float(u << 16); }
__device__ __forceinline__ float bf_hi(uint32_t u) { return __uint_as_float(u & 0xFFFF0000u); }

__device__ __forceinline__ void ldsm_x4(uint32_t* r, uint32_t addr) {
    asm volatile("ldmatrix.sync.aligned.m8n8.x4.shared.b16 {%0,%1,%2,%3}, [%4];"
        : "=r"(r[0]), "=r"(r[1]), "=r"(r[2]), "=r"(r[3]) : "r"(addr));
}
__device__ __forceinline__ void ldsm_x2t(uint32_t* r, uint32_t addr) {
    asm volatile("ldmatrix.sync.aligned.m8n8.x2.trans.shared.b16 {%0,%1}, [%2];"
        : "=r"(r[0]), "=r"(r[1]) : "r"(addr));
}
__device__ __forceinline__ void cpa16(uint32_t dst, const void* src, int valid) {
    asm volatile("cp.async.cg.shared.global [%0], [%1], 16, %2;"
        :: "r"(dst), "l"(src), "r"(valid ? 16 : 0));
}
#define CPA_COMMIT() asm volatile("cp.async.commit_group;" ::: "memory")
#define CPA_WAIT1()  asm volatile("cp.async.wait_group 1;" ::: "memory")

// ---------------- f32 -> bf16 conversion ----------------
__global__ void k_f2bf(const float4* __restrict__ src, uint2* __restrict__ dst, int n4) {
    int i = blockIdx.x * blockDim.x + threadIdx.x;
    if (i < n4) {
        float4 v = src[i];
        dst[i] = make_uint2(pack_bf16(v.x, v.y), pack_bf16(v.z, v.w));
    }
}

// ---------------- dtype detection ----------------
__global__ void k_detect(const void* ei) {
    const long long* p = (const long long*)ei;
    int ok = 1;
#pragma unroll
    for (int i = 0; i < 8; i++) {
        long long v = p[i];
        if (v < 0 || v >= NN) ok = 0;
    }
    g_is64 = ok;
}
__device__ __forceinline__ int idx_at(const void* p, long long i) {
    return g_is64 ? (int)((const long long*)p)[i] : ((const int*)p)[i];
}

// ---------------- degree / CSR ----------------
__global__ void k_zero_cnt() {
    int i = blockIdx.x * blockDim.x + threadIdx.x;
    if (i < NN) g_cnt[i] = 0;
}
__global__ void k_deg(const void* __restrict__ ei) {
    int e = blockIdx.x * blockDim.x + threadIdx.x;
    if (e < NE) atomicAdd(&g_cnt[idx_at(ei, (long long)NE + e)], 1);
}
__global__ void k_rsqrt() {
    int i = blockIdx.x * blockDim.x + threadIdx.x;
    if (i < NN) g_dinv[i] = rsqrtf((float)g_cnt[i] + 1.0f);
}

#define SCAN_T   1024
#define SCAN_CH  20
__global__ void __launch_bounds__(SCAN_T) k_scan() {
    __shared__ int s[SCAN_T];
    int tid = threadIdx.x;
    int base = tid * SCAN_CH;
    int local[SCAN_CH];
    int sum = 0;
#pragma unroll
    for (int i = 0; i < SCAN_CH; i++) {
        int idx = base + i;
        int v = (idx < NN) ? g_cnt[idx] : 0;
        local[i] = sum;
        sum += v;
    }
    s[tid] = sum;
    __syncthreads();
    for (int off = 1; off < SCAN_T; off <<= 1) {
        int v = (tid >= off) ? s[tid - off] : 0;
        __syncthreads();
        if (tid >= off) s[tid] += v;
        __syncthreads();
    }
    int pre = (tid > 0) ? s[tid - 1] : 0;
#pragma unroll
    for (int i = 0; i < SCAN_CH; i++) {
        int idx = base + i;
        if (idx < NN) {
            int v = pre + local[i];
            g_rowptr[idx] = v;
            g_cursor[idx] = v;
        }
    }
    if (tid == SCAN_T - 1) g_rowptr[NN] = NE;
}
__global__ void k_fill(const void* __restrict__ ei) {
    int e = blockIdx.x * blockDim.x + threadIdx.x;
    if (e < NE) {
        int src, dst;
        if (g_is64) {
            const long long* p = (const long long*)ei;
            src = (int)p[e]; dst = (int)p[NE + e];
        } else {
            const int* p = (const int*)ei;
            src = p[e]; dst = p[NE + e];
        }
        g_csrsrc[atomicAdd(&g_cursor[dst], 1)] = src;
    }
}

// ---------------- bf16 mma GEMM, cp.async 3-stage pipeline ----------------
// C[M,512] = A[M,K] @ B[K,512]; A,B bf16 in gmem; C bf16.
// BM=128, BN=128, BK=32. 256 thr = 8 warps (2x4), warp tile 64x32.
#define A_STR 40
#define B_STR 136
#define ABYTES (128 * A_STR * 2)             // 10240
#define BBYTES (32 * B_STR * 2)              // 8704
#define STG    (ABYTES + BBYTES)             // 18944
#define GEMM_SMEM (3 * STG)                  // 56832

__global__ void __launch_bounds__(256, 2) k_gemm_bf16(
    const uint16_t* __restrict__ A, const uint16_t* __restrict__ B,
    uint16_t* __restrict__ Cb, int M, int K)
{
    extern __shared__ __align__(16) uint16_t smem[];
    const uint32_t sb = smem_u32(smem);

    const int tid  = threadIdx.x;
    const int wid  = tid >> 5;
    const int lane = tid & 31;
    const int wm   = wid >> 2;
    const int wn   = wid & 3;
    const int n0   = blockIdx.x * 128;
    const int m0   = blockIdx.y * 128;
    const int NIT  = K >> 5;

    // cp.async loader lambdas (2 x 16B per thread for A and for B)
    const int ar0 = (tid >> 2);             // A rows: idx>>2
    const int ac0 = (tid & 3);              // A chunk
    const int br0 = (tid >> 4);             // B rows: idx>>4
    const int bc0 = (tid & 15);             // B chunk

    auto load_tile = [&](int it, int stage) {
        const int k0 = it << 5;
        const uint32_t base = sb + stage * STG;
#pragma unroll
        for (int i = 0; i < 2; i++) {
            int row = ar0 + i * 64;         // (tid + 256*i) >> 2
            uint32_t dst = base + row * (A_STR * 2) + ac0 * 16;
            const uint16_t* src = A + (size_t)(m0 + row) * K + k0 + ac0 * 8;
            cpa16(dst, src, (m0 + row) < M);
        }
#pragma unroll
        for (int i = 0; i < 2; i++) {
            int row = br0 + i * 16;         // (tid + 256*i) >> 4
            uint32_t dst = base + ABYTES + row * (B_STR * 2) + bc0 * 16;
            const uint16_t* src = B + (size_t)(k0 + row) * DH + n0 + bc0 * 8;
            cpa16(dst, src, 1);
        }
    };

    float acc[4][4][4];
#pragma unroll
    for (int mi = 0; mi < 4; mi++)
#pragma unroll
        for (int ni = 0; ni < 4; ni++)
#pragma unroll
            for (int q = 0; q < 4; q++) acc[mi][ni][q] = 0.0f;

    // prologue: stages 0,1 in flight
    load_tile(0, 0);
    CPA_COMMIT();
    if (NIT > 1) load_tile(1, 1);
    CPA_COMMIT();

    const int lr15 = lane & 15;
    const int lk8  = (lane >> 4) << 3;

    for (int it = 0; it < NIT; it++) {
        CPA_WAIT1();
        __syncthreads();

        int nxt = it + 2;
        if (nxt < NIT) load_tile(nxt, nxt % 3);
        CPA_COMMIT();

        const uint32_t aB = sb + (it % 3) * STG;
        const uint32_t bB = aB + ABYTES;

#pragma unroll
        for (int ks = 0; ks < 2; ks++) {
            const int kb = ks * 16;
            uint32_t af[4][4], bfr[4][2];
#pragma unroll
            for (int mi = 0; mi < 4; mi++) {
                uint32_t ad = aB +
                    (uint32_t)(((wm * 64 + mi * 16 + lr15) * A_STR + kb + lk8) * 2);
                ldsm_x4(af[mi], ad);
            }
#pragma unroll
            for (int ni = 0; ni < 4; ni++) {
                uint32_t bd = bB +
                    (uint32_t)(((kb + lr15) * B_STR + wn * 32 + ni * 8) * 2);
                ldsm_x2t(bfr[ni], bd);
            }
#pragma unroll
            for (int mi = 0; mi < 4; mi++)
#pragma unroll
                for (int ni = 0; ni < 4; ni++) {
                    asm volatile(
                        "mma.sync.aligned.m16n8k16.row.col.f32.bf16.bf16.f32 "
                        "{%0,%1,%2,%3}, {%4,%5,%6,%7}, {%8,%9}, {%0,%1,%2,%3};"
                        : "+f"(acc[mi][ni][0]), "+f"(acc[mi][ni][1]),
                          "+f"(acc[mi][ni][2]), "+f"(acc[mi][ni][3])
                        : "r"(af[mi][0]), "r"(af[mi][1]), "r"(af[mi][2]), "r"(af[mi][3]),
                          "r"(bfr[ni][0]), "r"(bfr[ni][1]));
                }
        }
    }

    // epilogue: pack fp32 acc -> bf16 pairs
    const int r = lane >> 2;
    const int c = lane & 3;
#pragma unroll
    for (int mi = 0; mi < 4; mi++) {
        int row = m0 + wm * 64 + mi * 16 + r;
#pragma unroll
        for (int ni = 0; ni < 4; ni++) {
            int col = n0 + wn * 32 + ni * 8 + c * 2;
            if (row < M)
                *(uint32_t*)(Cb + (size_t)row * DH + col) =
                    pack_bf16(acc[mi][ni][0], acc[mi][ni][1]);
            if (row + 8 < M)
                *(uint32_t*)(Cb + (size_t)(row + 8) * DH + col) =
                    pack_bf16(acc[mi][ni][2], acc[mi][ni][3]);
        }
    }
}

// ---------------- CSR gather (bf16 in) ----------------
template <int OBF>
__global__ void __launch_bounds__(256) k_gather(
    const uint16_t* __restrict__ h, const float* __restrict__ bias,
    void* __restrict__ outv)
{
    int n = blockIdx.x * 2 + threadIdx.y;
    if (n >= NN) return;
    int s = g_rowptr[n];
    int e = g_rowptr[n + 1];
    float dn = g_dinv[n];
    int c = threadIdx.x * 4;

    uint2 u = *(const uint2*)(h + (size_t)n * DH + c);
    float d2 = dn * dn;
    float a0 = bf_lo(u.x) * d2, a1 = bf_hi(u.x) * d2;
    float a2 = bf_lo(u.y) * d2, a3 = bf_hi(u.y) * d2;

    int j = s;
    for (; j + 3 < e; j += 4) {
        int s0 = g_csrsrc[j],     s1 = g_csrsrc[j + 1];
        int s2 = g_csrsrc[j + 2], s3 = g_csrsrc[j + 3];
        float c0 = g_dinv[s0] * dn, c1 = g_dinv[s1] * dn;
        float c2 = g_dinv[s2] * dn, c3 = g_dinv[s3] * dn;
        uint2 u0 = *(const uint2*)(h + (size_t)s0 * DH + c);
        uint2 u1 = *(const uint2*)(h + (size_t)s1 * DH + c);
        uint2 u2 = *(const uint2*)(h + (size_t)s2 * DH + c);
        uint2 u3 = *(const uint2*)(h + (size_t)s3 * DH + c);
        a0 = fmaf(bf_lo(u0.x), c0, a0); a1 = fmaf(bf_hi(u0.x), c0, a1);
        a2 = fmaf(bf_lo(u0.y), c0, a2); a3 = fmaf(bf_hi(u0.y), c0, a3);
        a0 = fmaf(bf_lo(u1.x), c1, a0); a1 = fmaf(bf_hi(u1.x), c1, a1);
        a2 = fmaf(bf_lo(u1.y), c1, a2); a3 = fmaf(bf_hi(u1.y), c1, a3);
        a0 = fmaf(bf_lo(u2.x), c2, a0); a1 = fmaf(bf_hi(u2.x), c2, a1);
        a2 = fmaf(bf_lo(u2.y), c2, a2); a3 = fmaf(bf_hi(u2.y), c2, a3);
        a0 = fmaf(bf_lo(u3.x), c3, a0); a1 = fmaf(bf_hi(u3.x), c3, a1);
        a2 = fmaf(bf_lo(u3.y), c3, a2); a3 = fmaf(bf_hi(u3.y), c3, a3);
    }
    for (; j < e; j++) {
        int s0 = g_csrsrc[j];
        float c0 = g_dinv[s0] * dn;
        uint2 u0 = *(const uint2*)(h + (size_t)s0 * DH + c);
        a0 = fmaf(bf_lo(u0.x), c0, a0); a1 = fmaf(bf_hi(u0.x), c0, a1);
        a2 = fmaf(bf_lo(u0.y), c0, a2); a3 = fmaf(bf_hi(u0.y), c0, a3);
    }

    float4 b = *(const float4*)(bias + c);
    a0 += b.x; a1 += b.y; a2 += b.z; a3 += b.w;
    if (OBF) {
        a0 = fmaxf(a0, 0.f); a1 = fmaxf(a1, 0.f);
        a2 = fmaxf(a2, 0.f); a3 = fmaxf(a3, 0.f);
        uint16_t* ob = (uint16_t*)outv;
        *(uint2*)(ob + (size_t)n * DH + c) =
            make_uint2(pack_bf16(a0, a1), pack_bf16(a2, a3));
    } else {
        float* of = (float*)outv;
        *(float4*)(of + (size_t)n * DH + c) = make_float4(a0, a1, a2, a3);
    }
}

// ---------------- segment max ----------------
__device__ __forceinline__ int lower_bound_batch(const void* batch, int val) {
    int lo = 0, hi = NN;
    while (lo < hi) {
        int mid = (lo + hi) >> 1;
        if (idx_at(batch, mid) < val) lo = mid + 1; else hi = mid;
    }
    return lo;
}
__global__ void k_segmax(const void* __restrict__ batch) {
    int g = blockIdx.x;
    int c = threadIdx.x;
    int s = lower_bound_batch(batch, g);
    int e = lower_bound_batch(batch, g + 1);
    float m = 0.0f;
    for (int n = s; n < e; n++)
        m = fmaxf(m, g_agg[(size_t)n * DH + c]);
    g_pool[g * DH + c] = m;
}

// ---------------- FC head ----------------
__global__ void __launch_bounds__(256) k_head(
    const float* __restrict__ A, const float* __restrict__ B,
    const float* __restrict__ bias, float* __restrict__ C,
    int N, int K, int mode,
    const float* __restrict__ gamma, const float* __restrict__ beta)
{
    const int BK = 32, BN = 32;
    __shared__ float As[BK][64];
    __shared__ float Bs[BK][BN];

    int tid = threadIdx.x;
    int colBase = blockIdx.x * BN;
    int ty = tid >> 4, tx = tid & 15;

    float acc[4][2] = {{0.f, 0.f}, {0.f, 0.f}, {0.f, 0.f}, {0.f, 0.f}};

    for (int k0 = 0; k0 < K; k0 += BK) {
        __syncthreads();
#pragma unroll
        for (int l = 0; l < 8; l++) {
            int idx = tid * 8 + l;
            int m = idx >> 5, k = idx & 31;
            As[k][m] = A[(size_t)m * K + k0 + k];
        }
#pragma unroll
        for (int l = 0; l < 4; l++) {
            int idx = tid * 4 + l;
            int k = idx >> 5, n = idx & 31;
            int col = colBase + n;
            Bs[k][n] = (col < N) ? B[(size_t)(k0 + k) * N + col] : 0.f;
        }
        __syncthreads();
#pragma unroll
        for (int k = 0; k < BK; k++) {
            float ra2[4], rb2[2];
#pragma unroll
            for (int i = 0; i < 4; i++) ra2[i] = As[k][ty * 4 + i];
#pragma unroll
            for (int j = 0; j < 2; j++) rb2[j] = Bs[k][tx * 2 + j];
#pragma unroll
            for (int i = 0; i < 4; i++)
#pragma unroll
                for (int j = 0; j < 2; j++)
                    acc[i][j] = fmaf(ra2[i], rb2[j], acc[i][j]);
        }
    }

    const float bninv = rsqrtf(1.0f + 1e-5f);
#pragma unroll
    for (int i = 0; i < 4; i++) {
#pragma unroll
        for (int j = 0; j < 2; j++) {
            int row = ty * 4 + i;
            int col = colBase + tx * 2 + j;
            if (col < N) {
                float z = acc[i][j] + bias[col];
                if (mode == 0) {
                    z = fmaxf(z, 0.f);
                } else {
                    z = z * gamma[col] * bninv + beta[col];
                    z = 1.0f / (1.0f + expf(-z));
                }
                C[(size_t)row * N + col] = z;
            }
        }
    }
}

// ---------------- host ----------------
extern "C" void kernel_launch(void* const* d_in, const int* in_sizes, int n_in,
                              void* d_out, int out_size)
{
    const float* x     = (const float*)d_in[0];
    const void*  ei    = d_in[1];
    const void*  batch = d_in[2];
    const float* Wg1   = (const float*)d_in[3];
    const float* bg1   = (const float*)d_in[4];
    const float* Wg2   = (const float*)d_in[5];
    const float* bg2   = (const float*)d_in[6];
    const float* W1    = (const float*)d_in[7];
    const float* b1    = (const float*)d_in[8];
    const float* W2    = (const float*)d_in[9];
    const float* b2    = (const float*)d_in[10];
    const float* gamma = (const float*)d_in[11];
    const float* beta  = (const float*)d_in[12];
    float* out = (float*)d_out;

    uint16_t *p_xbf, *p_w1bf, *p_w2bf, *p_hbf, *p_aggbf, *p_h2bf;
    float *p_agg, *p_pool, *p_fc1;
    cudaGetSymbolAddress((void**)&p_xbf,   g_xbf);
    cudaGetSymbolAddress((void**)&p_w1bf,  g_w1bf);
    cudaGetSymbolAddress((void**)&p_w2bf,  g_w2bf);
    cudaGetSymbolAddress((void**)&p_hbf,   g_hbf);
    cudaGetSymbolAddress((void**)&p_aggbf, g_aggbf);
    cudaGetSymbolAddress((void**)&p_h2bf,  g_h2bf);
    cudaGetSymbolAddress((void**)&p_agg,   g_agg);
    cudaGetSymbolAddress((void**)&p_pool,  g_pool);
    cudaGetSymbolAddress((void**)&p_fc1,   g_fc1);

    static int smem_set = 0;
    if (!smem_set) {
        cudaFuncSetAttribute(k_gemm_bf16,
            cudaFuncAttributeMaxDynamicSharedMemorySize, GEMM_SMEM);
        smem_set = 1;
    }

    k_detect<<<1, 1>>>(ei);

    // conversions (independent of CSR build; interleave)
    k_f2bf<<<(NN * DIN / 4 + 255) / 256, 256>>>((const float4*)x, (uint2*)p_xbf, NN * DIN / 4);
    k_f2bf<<<(DIN * DH / 4 + 255) / 256, 256>>>((const float4*)Wg1, (uint2*)p_w1bf, DIN * DH / 4);
    k_f2bf<<<(DH * DH / 4 + 255) / 256, 256>>>((const float4*)Wg2, (uint2*)p_w2bf, DH * DH / 4);

    k_zero_cnt<<<(NN + 255) / 256, 256>>>();
    k_deg<<<(NE + 255) / 256, 256>>>(ei);
    k_rsqrt<<<(NN + 255) / 256, 256>>>();
    k_scan<<<1, SCAN_T>>>();
    k_fill<<<(NE + 255) / 256, 256>>>(ei);

    dim3 gg(DH / 128, (NN + 127) / 128);
    k_gemm_bf16<<<gg, 256, GEMM_SMEM>>>(p_xbf, p_w1bf, p_hbf, NN, DIN);
    k_gather<1><<<(NN + 1) / 2, dim3(128, 2)>>>(p_hbf, bg1, p_aggbf);

    k_gemm_bf16<<<gg, 256, GEMM_SMEM>>>(p_aggbf, p_w2bf, p_h2bf, NN, DH);
    k_gather<0><<<(NN + 1) / 2, dim3(128, 2)>>>(p_h2bf, bg2, p_agg);

    k_segmax<<<NG, DH>>>(batch);

    k_head<<<(DFC + 31) / 32, 256>>>(p_pool, W1, b1, p_fc1, DFC, DH, 0, nullptr, nullptr);
    k_head<<<(DOUT + 31) / 32, 256>>>(p_fc1, W2, b2, out, DOUT, DFC, 1, gamma, beta);
}